// round 1
// baseline (speedup 1.0000x reference)
#include <cuda_runtime.h>
#include <math.h>

#define S_LEN 4096
#define HIDN  2048
#define NH    16
#define NKV   8
#define DH    128
#define KVW   (NKV*DH)      // 1024
#define ATT_SCALE 0.08838834764831845f   // 1/sqrt(128)

// -------- scratch (device globals: allocation-free) --------
__device__ float g_q[(size_t)S_LEN * HIDN];   // 32 MB
__device__ float g_k[(size_t)S_LEN * KVW];    // 16 MB
__device__ float g_v[(size_t)S_LEN * KVW];    // 16 MB
__device__ float g_o[(size_t)S_LEN * HIDN];   // 32 MB

// ============================================================
// GEMM: C[m][n] = sum_k A[m][k]*B[n][k] + bias[n]
// BM=BN=128, BK=16, 256 threads, 8x8 per-thread tile
// ============================================================
__global__ __launch_bounds__(256)
void gemm_tn(const float* __restrict__ A, const float* __restrict__ B,
             const float* __restrict__ bias, float* __restrict__ C,
             int M, int N, int K)
{
    __shared__ float As[16 * 132];
    __shared__ float Bs[16 * 132];

    const int tid = threadIdx.x;
    const int tx = tid & 15, ty = tid >> 4;
    const int bm = blockIdx.y * 128, bn = blockIdx.x * 128;

    float acc[8][8];
#pragma unroll
    for (int i = 0; i < 8; i++)
#pragma unroll
        for (int j = 0; j < 8; j++) acc[i][j] = 0.f;

    for (int k0 = 0; k0 < K; k0 += 16) {
#pragma unroll
        for (int t = tid; t < 512; t += 256) {
            int r = t >> 2, kq = (t & 3) << 2;
            float4 a = *(const float4*)(A + (size_t)(bm + r) * K + k0 + kq);
            As[(kq + 0) * 132 + r] = a.x;
            As[(kq + 1) * 132 + r] = a.y;
            As[(kq + 2) * 132 + r] = a.z;
            As[(kq + 3) * 132 + r] = a.w;
            float4 b = *(const float4*)(B + (size_t)(bn + r) * K + k0 + kq);
            Bs[(kq + 0) * 132 + r] = b.x;
            Bs[(kq + 1) * 132 + r] = b.y;
            Bs[(kq + 2) * 132 + r] = b.z;
            Bs[(kq + 3) * 132 + r] = b.w;
        }
        __syncthreads();

#pragma unroll
        for (int kk = 0; kk < 16; kk++) {
            float4 a0 = *(const float4*)(As + kk * 132 + ty * 8);
            float4 a1 = *(const float4*)(As + kk * 132 + ty * 8 + 4);
            float4 b0 = *(const float4*)(Bs + kk * 132 + tx * 8);
            float4 b1 = *(const float4*)(Bs + kk * 132 + tx * 8 + 4);
            float av[8] = {a0.x, a0.y, a0.z, a0.w, a1.x, a1.y, a1.z, a1.w};
            float bv[8] = {b0.x, b0.y, b0.z, b0.w, b1.x, b1.y, b1.z, b1.w};
#pragma unroll
            for (int i = 0; i < 8; i++)
#pragma unroll
                for (int j = 0; j < 8; j++)
                    acc[i][j] += av[i] * bv[j];
        }
        __syncthreads();
    }

    float bfr[8];
#pragma unroll
    for (int j = 0; j < 8; j++) bfr[j] = bias ? bias[bn + tx * 8 + j] : 0.f;

#pragma unroll
    for (int i = 0; i < 8; i++) {
        int row = bm + ty * 8 + i;
        float4 o0, o1;
        o0.x = acc[i][0] + bfr[0]; o0.y = acc[i][1] + bfr[1];
        o0.z = acc[i][2] + bfr[2]; o0.w = acc[i][3] + bfr[3];
        o1.x = acc[i][4] + bfr[4]; o1.y = acc[i][5] + bfr[5];
        o1.z = acc[i][6] + bfr[6]; o1.w = acc[i][7] + bfr[7];
        *(float4*)(C + (size_t)row * N + bn + tx * 8)     = o0;
        *(float4*)(C + (size_t)row * N + bn + tx * 8 + 4) = o1;
    }
}

// ============================================================
// Fused RMSNorm + RoPE, in-place on q (heads 0..15) / k (16..23)
// one 128-thread block per (token, head)
// ============================================================
__global__ __launch_bounds__(128)
void rmsrope_kernel(float* __restrict__ q, float* __restrict__ k,
                    const float* __restrict__ cosb, const float* __restrict__ sinb,
                    const float* __restrict__ qw, const float* __restrict__ kw)
{
    int s  = blockIdx.x;
    int hh = blockIdx.y;
    int d  = threadIdx.x;

    float* base;
    const float* w;
    if (hh < NH) { base = q + (size_t)s * HIDN + hh * DH;        w = qw; }
    else         { base = k + (size_t)s * KVW  + (hh - NH) * DH; w = kw; }

    float val = base[d];
    float ss  = val * val;
#pragma unroll
    for (int off = 16; off >= 1; off >>= 1)
        ss += __shfl_xor_sync(0xffffffffu, ss, off);

    __shared__ float red[4];
    __shared__ float sv[128];
    int lane = d & 31, wid = d >> 5;
    if (lane == 0) red[wid] = ss;
    __syncthreads();
    float tot = red[0] + red[1] + red[2] + red[3];
    float inv = rsqrtf(tot * (1.f / 128.f) + 1e-6f);

    float nv = w[d] * val * inv;
    sv[d] = nv;
    __syncthreads();
    float other = (d < 64) ? -sv[d + 64] : sv[d - 64];
    base[d] = nv * cosb[(size_t)s * DH + d] + other * sinb[(size_t)s * DH + d];
}

// ============================================================
// Flash attention, fp32, causal. BM=BN=64, D=128.
// grid (64 qtiles, 16 heads), 256 threads.
// ============================================================
#define QK_PAD 132
#define ATTN_SMEM_FLOATS (64*QK_PAD*2 + 64*128 + 64*64)

__global__ __launch_bounds__(256)
void attn_kernel(const float* __restrict__ Q, const float* __restrict__ K,
                 const float* __restrict__ V, float* __restrict__ O)
{
    extern __shared__ float sm[];
    float* Qs = sm;                   // [64][132]
    float* Ks = Qs + 64 * QK_PAD;     // [64][132]
    float* Vs = Ks + 64 * QK_PAD;     // [64][128]
    float* Ps = Vs + 64 * 128;        // [64][64]

    const int tid = threadIdx.x;
    const int tx = tid & 15, ty = tid >> 4;
    const int h  = blockIdx.y;
    const int qt = (gridDim.x - 1) - blockIdx.x;   // long tiles first
    const int row0 = qt * 64;
    const int kh = h >> 1;                         // GQA: reps = 2

    // load Q tile (coalesced float4)
#pragma unroll
    for (int t = tid; t < 2048; t += 256) {
        int r = t >> 5, d4 = (t & 31) << 2;
        *(float4*)(Qs + r * QK_PAD + d4) =
            *(const float4*)(Q + (size_t)(row0 + r) * HIDN + h * DH + d4);
    }

    float acc[4][8];
#pragma unroll
    for (int i = 0; i < 4; i++)
#pragma unroll
        for (int c = 0; c < 8; c++) acc[i][c] = 0.f;
    float m_i[4], l_i[4];
#pragma unroll
    for (int i = 0; i < 4; i++) { m_i[i] = -INFINITY; l_i[i] = 0.f; }

    for (int jt = 0; jt <= qt; jt++) {
        const int col0 = jt * 64;
        __syncthreads();   // protect Ks/Vs/Ps from previous iteration readers
#pragma unroll
        for (int t = tid; t < 2048; t += 256) {
            int r = t >> 5, d4 = (t & 31) << 2;
            *(float4*)(Ks + r * QK_PAD + d4) =
                *(const float4*)(K + (size_t)(col0 + r) * KVW + kh * DH + d4);
            *(float4*)(Vs + r * 128 + d4) =
                *(const float4*)(V + (size_t)(col0 + r) * KVW + kh * DH + d4);
        }
        __syncthreads();

        // scores: 4x4 per thread over d=128
        float sc[4][4];
#pragma unroll
        for (int i = 0; i < 4; i++)
#pragma unroll
            for (int j = 0; j < 4; j++) sc[i][j] = 0.f;

#pragma unroll 8
        for (int d4 = 0; d4 < 32; d4++) {
            float4 qv[4], kv[4];
#pragma unroll
            for (int i = 0; i < 4; i++)
                qv[i] = *(const float4*)(Qs + (ty * 4 + i) * QK_PAD + d4 * 4);
#pragma unroll
            for (int j = 0; j < 4; j++)
                kv[j] = *(const float4*)(Ks + (tx * 4 + j) * QK_PAD + d4 * 4);
#pragma unroll
            for (int i = 0; i < 4; i++)
#pragma unroll
                for (int j = 0; j < 4; j++) {
                    sc[i][j] += qv[i].x * kv[j].x;
                    sc[i][j] += qv[i].y * kv[j].y;
                    sc[i][j] += qv[i].z * kv[j].z;
                    sc[i][j] += qv[i].w * kv[j].w;
                }
        }

        const bool diag = (jt == qt);
#pragma unroll
        for (int i = 0; i < 4; i++) {
#pragma unroll
            for (int j = 0; j < 4; j++) {
                sc[i][j] *= ATT_SCALE;
                if (diag && (tx * 4 + j > ty * 4 + i)) sc[i][j] = -1e30f;
            }
            // row max across the 16 tx lanes
            float mx = fmaxf(fmaxf(sc[i][0], sc[i][1]), fmaxf(sc[i][2], sc[i][3]));
#pragma unroll
            for (int off = 8; off >= 1; off >>= 1)
                mx = fmaxf(mx, __shfl_xor_sync(0xffffffffu, mx, off));

            float mn = fmaxf(m_i[i], mx);
            float alpha = (m_i[i] == -INFINITY) ? 0.f : __expf(m_i[i] - mn);
            float ls = 0.f;
#pragma unroll
            for (int j = 0; j < 4; j++) {
                float p = __expf(sc[i][j] - mn);
                sc[i][j] = p;
                ls += p;
            }
#pragma unroll
            for (int off = 8; off >= 1; off >>= 1)
                ls += __shfl_xor_sync(0xffffffffu, ls, off);

            l_i[i] = l_i[i] * alpha + ls;
            m_i[i] = mn;
#pragma unroll
            for (int c = 0; c < 8; c++) acc[i][c] *= alpha;
        }

        // write P tile (vectorized, conflict-light)
#pragma unroll
        for (int i = 0; i < 4; i++) {
            float4 pw = make_float4(sc[i][0], sc[i][1], sc[i][2], sc[i][3]);
            *(float4*)(Ps + (ty * 4 + i) * 64 + tx * 4) = pw;
        }
        __syncthreads();

        // PV: acc[4][8] += P[4][64] * V[64][8]
#pragma unroll 4
        for (int kk = 0; kk < 64; kk++) {
            float pv0 = Ps[(ty * 4 + 0) * 64 + kk];
            float pv1 = Ps[(ty * 4 + 1) * 64 + kk];
            float pv2 = Ps[(ty * 4 + 2) * 64 + kk];
            float pv3 = Ps[(ty * 4 + 3) * 64 + kk];
            float4 v0 = *(const float4*)(Vs + kk * 128 + tx * 8);
            float4 v1 = *(const float4*)(Vs + kk * 128 + tx * 8 + 4);
            float vv[8] = {v0.x, v0.y, v0.z, v0.w, v1.x, v1.y, v1.z, v1.w};
            float pv[4] = {pv0, pv1, pv2, pv3};
#pragma unroll
            for (int i = 0; i < 4; i++)
#pragma unroll
                for (int c = 0; c < 8; c++)
                    acc[i][c] += pv[i] * vv[c];
        }
    }

    // epilogue: O[row][h*128 + col] = acc / l
#pragma unroll
    for (int i = 0; i < 4; i++) {
        float inv = 1.f / l_i[i];
        int row = row0 + ty * 4 + i;
        float4 o0, o1;
        o0.x = acc[i][0] * inv; o0.y = acc[i][1] * inv;
        o0.z = acc[i][2] * inv; o0.w = acc[i][3] * inv;
        o1.x = acc[i][4] * inv; o1.y = acc[i][5] * inv;
        o1.z = acc[i][6] * inv; o1.w = acc[i][7] * inv;
        *(float4*)(O + (size_t)row * HIDN + h * DH + tx * 8)     = o0;
        *(float4*)(O + (size_t)row * HIDN + h * DH + tx * 8 + 4) = o1;
    }
}

// ============================================================
// launch
// ============================================================
extern "C" void kernel_launch(void* const* d_in, const int* in_sizes, int n_in,
                              void* d_out, int out_size)
{
    const float* x    = (const float*)d_in[0];
    const float* cosb = (const float*)d_in[1];
    const float* sinb = (const float*)d_in[2];
    // d_in[3] = mask: ignored (exactly causal, implemented analytically)
    const float* Wq = (const float*)d_in[4];
    const float* bq = (const float*)d_in[5];
    const float* Wk = (const float*)d_in[6];
    const float* bk = (const float*)d_in[7];
    const float* Wv = (const float*)d_in[8];
    const float* bv = (const float*)d_in[9];
    const float* Wo = (const float*)d_in[10];
    const float* qw = (const float*)d_in[11];
    const float* kw = (const float*)d_in[12];
    float* out = (float*)d_out;

    float *qp, *kp, *vp, *op;
    cudaGetSymbolAddress((void**)&qp, g_q);
    cudaGetSymbolAddress((void**)&kp, g_k);
    cudaGetSymbolAddress((void**)&vp, g_v);
    cudaGetSymbolAddress((void**)&op, g_o);

    const int attn_smem = ATTN_SMEM_FLOATS * (int)sizeof(float);  // 116736 B
    cudaFuncSetAttribute(attn_kernel, cudaFuncAttributeMaxDynamicSharedMemorySize,
                         attn_smem);

    dim3 blk(256);
    gemm_tn<<<dim3(16, 32), blk>>>(x, Wq, bq, qp, S_LEN, HIDN, HIDN);
    gemm_tn<<<dim3(8, 32),  blk>>>(x, Wk, bk, kp, S_LEN, KVW,  HIDN);
    gemm_tn<<<dim3(8, 32),  blk>>>(x, Wv, bv, vp, S_LEN, KVW,  HIDN);

    rmsrope_kernel<<<dim3(S_LEN, NH + NKV), 128>>>(qp, kp, cosb, sinb, qw, kw);

    attn_kernel<<<dim3(64, NH), 256, attn_smem>>>(qp, kp, vp, op);

    gemm_tn<<<dim3(16, 32), blk>>>(op, Wo, nullptr, out, S_LEN, HIDN, HIDN);
}

// round 3
// speedup vs baseline: 1.3481x; 1.3481x over previous
#include <cuda_runtime.h>
#include <math.h>
#include <cstdint>

#define S_LEN 4096
#define HIDN  2048
#define NH    16
#define NKV   8
#define DH    128
#define KVW   (NKV*DH)      // 1024
#define ATT_SCALE 0.08838834764831845f   // 1/sqrt(128)

// -------- scratch (device globals: allocation-free) --------
__device__ float g_q[(size_t)S_LEN * HIDN];   // 32 MB
__device__ float g_k[(size_t)S_LEN * KVW];    // 16 MB
__device__ float g_v[(size_t)S_LEN * KVW];    // 16 MB
__device__ float g_o[(size_t)S_LEN * HIDN];   // 32 MB

__device__ __forceinline__ float to_tf32(float x) {
    float r;
    asm("cvt.rna.tf32.f32 %0, %1;" : "=f"(r) : "f"(x));
    return r;
}

// warp-level tf32 MMA: D(16x8) += A(16x8) * B(8x8), row.col
__device__ __forceinline__ void mma_tf32(float* d, const float* a, const float* b) {
    asm volatile(
        "mma.sync.aligned.m16n8k8.row.col.f32.tf32.tf32.f32 "
        "{%0,%1,%2,%3}, {%4,%5,%6,%7}, {%8,%9}, {%0,%1,%2,%3};"
        : "+f"(d[0]), "+f"(d[1]), "+f"(d[2]), "+f"(d[3])
        : "r"(__float_as_uint(a[0])), "r"(__float_as_uint(a[1])),
          "r"(__float_as_uint(a[2])), "r"(__float_as_uint(a[3])),
          "r"(__float_as_uint(b[0])), "r"(__float_as_uint(b[1])));
}

// ============================================================
// Tensor-core GEMM (tf32 mma.sync): C[m][n] = sum_k A[m][k]*B[n][k] + bias[n]
// BM=BN=128, BK=32, 256 threads (8 warps, 4x2), warp tile 32x64.
// ============================================================
#define SPAD 36   // 32 + 4 floats padding

__global__ __launch_bounds__(256)
void gemm_mma(const float* __restrict__ A, const float* __restrict__ B,
              const float* __restrict__ bias, float* __restrict__ C,
              int M, int N, int K)
{
    __shared__ float As[128 * SPAD];
    __shared__ float Bs[128 * SPAD];

    const int tid  = threadIdx.x;
    const int lane = tid & 31, wid = tid >> 5;
    const int g = lane >> 2, t = lane & 3;          // group / thread-in-group
    const int wm = wid & 3, wn = wid >> 2;          // warp grid 4(M) x 2(N)
    const int bm = blockIdx.y * 128, bn = blockIdx.x * 128;

    const int lr = tid >> 3;          // 0..31  (global load row stripe)
    const int lc = (tid & 7) << 2;    // 0,4,..,28

    float acc[2][8][4];
#pragma unroll
    for (int i = 0; i < 2; i++)
#pragma unroll
        for (int j = 0; j < 8; j++)
#pragma unroll
            for (int c = 0; c < 4; c++) acc[i][j][c] = 0.f;

    float4 ra[4], rb[4];

#define LOAD_TILE(k0)                                                        \
    {                                                                        \
        _Pragma("unroll")                                                    \
        for (int i = 0; i < 4; i++) {                                        \
            ra[i] = *(const float4*)(A + (size_t)(bm + lr + 32 * i) * K + (k0) + lc); \
            rb[i] = *(const float4*)(B + (size_t)(bn + lr + 32 * i) * K + (k0) + lc); \
        }                                                                    \
    }

#define STORE_TILE()                                                         \
    {                                                                        \
        _Pragma("unroll")                                                    \
        for (int i = 0; i < 4; i++) {                                        \
            float4 a = ra[i];                                                \
            a.x = to_tf32(a.x); a.y = to_tf32(a.y);                          \
            a.z = to_tf32(a.z); a.w = to_tf32(a.w);                          \
            *(float4*)(As + (lr + 32 * i) * SPAD + lc) = a;                  \
            float4 b = rb[i];                                                \
            b.x = to_tf32(b.x); b.y = to_tf32(b.y);                          \
            b.z = to_tf32(b.z); b.w = to_tf32(b.w);                          \
            *(float4*)(Bs + (lr + 32 * i) * SPAD + lc) = b;                  \
        }                                                                    \
    }

    LOAD_TILE(0);
    STORE_TILE();
    __syncthreads();

    const int nk = K >> 5;
    const int ab = wm * 32;   // warp M base in As
    const int bb = wn * 64;   // warp N base in Bs

    for (int it = 0; it < nk; ++it) {
        if (it + 1 < nk) LOAD_TILE((it + 1) << 5);

#pragma unroll
        for (int ks = 0; ks < 4; ks++) {
            float afr[2][4];
#pragma unroll
            for (int i = 0; i < 2; i++) {
                const float* ap = As + (ab + i * 16 + g) * SPAD + ks * 8 + t;
                afr[i][0] = ap[0];
                afr[i][1] = ap[8 * SPAD];
                afr[i][2] = ap[4];
                afr[i][3] = ap[8 * SPAD + 4];
            }
            float bfr[8][2];
#pragma unroll
            for (int j = 0; j < 8; j++) {
                const float* bp = Bs + (bb + j * 8 + g) * SPAD + ks * 8 + t;
                bfr[j][0] = bp[0];
                bfr[j][1] = bp[4];
            }
#pragma unroll
            for (int i = 0; i < 2; i++)
#pragma unroll
                for (int j = 0; j < 8; j++)
                    mma_tf32(acc[i][j], afr[i], bfr[j]);
        }
        __syncthreads();
        if (it + 1 < nk) {
            STORE_TILE();
            __syncthreads();
        }
    }

    // epilogue
#pragma unroll
    for (int j = 0; j < 8; j++) {
        const int col = bn + wn * 64 + j * 8 + 2 * t;
        float2 bv = make_float2(0.f, 0.f);
        if (bias) { bv.x = bias[col]; bv.y = bias[col + 1]; }
#pragma unroll
        for (int i = 0; i < 2; i++) {
            const int row = bm + wm * 32 + i * 16 + g;
            float2 o0 = make_float2(acc[i][j][0] + bv.x, acc[i][j][1] + bv.y);
            float2 o1 = make_float2(acc[i][j][2] + bv.x, acc[i][j][3] + bv.y);
            *(float2*)(C + (size_t)row * N + col)       = o0;
            *(float2*)(C + (size_t)(row + 8) * N + col) = o1;
        }
    }
#undef LOAD_TILE
#undef STORE_TILE
}

// ============================================================
// Fused RMSNorm + RoPE, in-place on q (heads 0..15) / k (16..23)
// ============================================================
__global__ __launch_bounds__(128)
void rmsrope_kernel(float* __restrict__ q, float* __restrict__ k,
                    const float* __restrict__ cosb, const float* __restrict__ sinb,
                    const float* __restrict__ qw, const float* __restrict__ kw)
{
    int s  = blockIdx.x;
    int hh = blockIdx.y;
    int d  = threadIdx.x;

    float* base;
    const float* w;
    if (hh < NH) { base = q + (size_t)s * HIDN + hh * DH;        w = qw; }
    else         { base = k + (size_t)s * KVW  + (hh - NH) * DH; w = kw; }

    float val = base[d];
    float ss  = val * val;
#pragma unroll
    for (int off = 16; off >= 1; off >>= 1)
        ss += __shfl_xor_sync(0xffffffffu, ss, off);

    __shared__ float red[4];
    __shared__ float sv[128];
    int lane = d & 31, wid = d >> 5;
    if (lane == 0) red[wid] = ss;
    __syncthreads();
    float tot = red[0] + red[1] + red[2] + red[3];
    float inv = rsqrtf(tot * (1.f / 128.f) + 1e-6f);

    float nv = w[d] * val * inv;
    sv[d] = nv;
    __syncthreads();
    float other = (d < 64) ? -sv[d + 64] : sv[d - 64];
    base[d] = nv * cosb[(size_t)s * DH + d] + other * sinb[(size_t)s * DH + d];
}

// ============================================================
// Flash attention, fp32, causal. BM=BN=64, D=128.
// ============================================================
#define QK_PAD 132
#define ATTN_SMEM_FLOATS (64*QK_PAD*2 + 64*128 + 64*64)

__global__ __launch_bounds__(256)
void attn_kernel(const float* __restrict__ Q, const float* __restrict__ K,
                 const float* __restrict__ V, float* __restrict__ O)
{
    extern __shared__ float sm[];
    float* Qs = sm;                   // [64][132]
    float* Ks = Qs + 64 * QK_PAD;     // [64][132]
    float* Vs = Ks + 64 * QK_PAD;     // [64][128]
    float* Ps = Vs + 64 * 128;        // [64][64]

    const int tid = threadIdx.x;
    const int tx = tid & 15, ty = tid >> 4;
    const int h  = blockIdx.y;
    const int qt = (gridDim.x - 1) - blockIdx.x;   // long tiles first
    const int row0 = qt * 64;
    const int kh = h >> 1;                         // GQA: reps = 2

#pragma unroll
    for (int t = tid; t < 2048; t += 256) {
        int r = t >> 5, d4 = (t & 31) << 2;
        *(float4*)(Qs + r * QK_PAD + d4) =
            *(const float4*)(Q + (size_t)(row0 + r) * HIDN + h * DH + d4);
    }

    float acc[4][8];
#pragma unroll
    for (int i = 0; i < 4; i++)
#pragma unroll
        for (int c = 0; c < 8; c++) acc[i][c] = 0.f;
    float m_i[4], l_i[4];
#pragma unroll
    for (int i = 0; i < 4; i++) { m_i[i] = -INFINITY; l_i[i] = 0.f; }

    for (int jt = 0; jt <= qt; jt++) {
        const int col0 = jt * 64;
        __syncthreads();
#pragma unroll
        for (int t = tid; t < 2048; t += 256) {
            int r = t >> 5, d4 = (t & 31) << 2;
            *(float4*)(Ks + r * QK_PAD + d4) =
                *(const float4*)(K + (size_t)(col0 + r) * KVW + kh * DH + d4);
            *(float4*)(Vs + r * 128 + d4) =
                *(const float4*)(V + (size_t)(col0 + r) * KVW + kh * DH + d4);
        }
        __syncthreads();

        float sc[4][4];
#pragma unroll
        for (int i = 0; i < 4; i++)
#pragma unroll
            for (int j = 0; j < 4; j++) sc[i][j] = 0.f;

#pragma unroll 8
        for (int d4 = 0; d4 < 32; d4++) {
            float4 qv[4], kv[4];
#pragma unroll
            for (int i = 0; i < 4; i++)
                qv[i] = *(const float4*)(Qs + (ty * 4 + i) * QK_PAD + d4 * 4);
#pragma unroll
            for (int j = 0; j < 4; j++)
                kv[j] = *(const float4*)(Ks + (tx * 4 + j) * QK_PAD + d4 * 4);
#pragma unroll
            for (int i = 0; i < 4; i++)
#pragma unroll
                for (int j = 0; j < 4; j++) {
                    sc[i][j] += qv[i].x * kv[j].x;
                    sc[i][j] += qv[i].y * kv[j].y;
                    sc[i][j] += qv[i].z * kv[j].z;
                    sc[i][j] += qv[i].w * kv[j].w;
                }
        }

        const bool diag = (jt == qt);
#pragma unroll
        for (int i = 0; i < 4; i++) {
#pragma unroll
            for (int j = 0; j < 4; j++) {
                sc[i][j] *= ATT_SCALE;
                if (diag && (tx * 4 + j > ty * 4 + i)) sc[i][j] = -1e30f;
            }
            float mx = fmaxf(fmaxf(sc[i][0], sc[i][1]), fmaxf(sc[i][2], sc[i][3]));
#pragma unroll
            for (int off = 8; off >= 1; off >>= 1)
                mx = fmaxf(mx, __shfl_xor_sync(0xffffffffu, mx, off));

            float mn = fmaxf(m_i[i], mx);
            float alpha = (m_i[i] == -INFINITY) ? 0.f : __expf(m_i[i] - mn);
            float ls = 0.f;
#pragma unroll
            for (int j = 0; j < 4; j++) {
                float p = __expf(sc[i][j] - mn);
                sc[i][j] = p;
                ls += p;
            }
#pragma unroll
            for (int off = 8; off >= 1; off >>= 1)
                ls += __shfl_xor_sync(0xffffffffu, ls, off);

            l_i[i] = l_i[i] * alpha + ls;
            m_i[i] = mn;
#pragma unroll
            for (int c = 0; c < 8; c++) acc[i][c] *= alpha;
        }

#pragma unroll
        for (int i = 0; i < 4; i++) {
            float4 pw = make_float4(sc[i][0], sc[i][1], sc[i][2], sc[i][3]);
            *(float4*)(Ps + (ty * 4 + i) * 64 + tx * 4) = pw;
        }
        __syncthreads();

#pragma unroll 4
        for (int kk = 0; kk < 64; kk++) {
            float pv0 = Ps[(ty * 4 + 0) * 64 + kk];
            float pv1 = Ps[(ty * 4 + 1) * 64 + kk];
            float pv2 = Ps[(ty * 4 + 2) * 64 + kk];
            float pv3 = Ps[(ty * 4 + 3) * 64 + kk];
            float4 v0 = *(const float4*)(Vs + kk * 128 + tx * 8);
            float4 v1 = *(const float4*)(Vs + kk * 128 + tx * 8 + 4);
            float vv[8] = {v0.x, v0.y, v0.z, v0.w, v1.x, v1.y, v1.z, v1.w};
            float pv[4] = {pv0, pv1, pv2, pv3};
#pragma unroll
            for (int i = 0; i < 4; i++)
#pragma unroll
                for (int c = 0; c < 8; c++)
                    acc[i][c] += pv[i] * vv[c];
        }
    }

#pragma unroll
    for (int i = 0; i < 4; i++) {
        float inv = 1.f / l_i[i];
        int row = row0 + ty * 4 + i;
        float4 o0, o1;
        o0.x = acc[i][0] * inv; o0.y = acc[i][1] * inv;
        o0.z = acc[i][2] * inv; o0.w = acc[i][3] * inv;
        o1.x = acc[i][4] * inv; o1.y = acc[i][5] * inv;
        o1.z = acc[i][6] * inv; o1.w = acc[i][7] * inv;
        *(float4*)(O + (size_t)row * HIDN + h * DH + tx * 8)     = o0;
        *(float4*)(O + (size_t)row * HIDN + h * DH + tx * 8 + 4) = o1;
    }
}

// ============================================================
// launch
// ============================================================
extern "C" void kernel_launch(void* const* d_in, const int* in_sizes, int n_in,
                              void* d_out, int out_size)
{
    const float* x    = (const float*)d_in[0];
    const float* cosb = (const float*)d_in[1];
    const float* sinb = (const float*)d_in[2];
    // d_in[3] = mask: ignored (exactly causal, implemented analytically)
    const float* Wq = (const float*)d_in[4];
    const float* bq = (const float*)d_in[5];
    const float* Wk = (const float*)d_in[6];
    const float* bk = (const float*)d_in[7];
    const float* Wv = (const float*)d_in[8];
    const float* bv = (const float*)d_in[9];
    const float* Wo = (const float*)d_in[10];
    const float* qw = (const float*)d_in[11];
    const float* kw = (const float*)d_in[12];
    float* out = (float*)d_out;

    float *qp, *kp, *vp, *op;
    cudaGetSymbolAddress((void**)&qp, g_q);
    cudaGetSymbolAddress((void**)&kp, g_k);
    cudaGetSymbolAddress((void**)&vp, g_v);
    cudaGetSymbolAddress((void**)&op, g_o);

    const int attn_smem = ATTN_SMEM_FLOATS * (int)sizeof(float);  // 116736 B
    cudaFuncSetAttribute(attn_kernel, cudaFuncAttributeMaxDynamicSharedMemorySize,
                         attn_smem);

    dim3 blk(256);
    gemm_mma<<<dim3(16, 32), blk>>>(x, Wq, bq, qp, S_LEN, HIDN, HIDN);
    gemm_mma<<<dim3(8, 32),  blk>>>(x, Wk, bk, kp, S_LEN, KVW,  HIDN);
    gemm_mma<<<dim3(8, 32),  blk>>>(x, Wv, bv, vp, S_LEN, KVW,  HIDN);

    rmsrope_kernel<<<dim3(S_LEN, NH + NKV), 128>>>(qp, kp, cosb, sinb, qw, kw);

    attn_kernel<<<dim3(64, NH), 256, attn_smem>>>(qp, kp, vp, op);

    gemm_mma<<<dim3(16, 32), blk>>>(op, Wo, nullptr, out, S_LEN, HIDN, HIDN);
}

// round 5
// speedup vs baseline: 4.7087x; 3.4929x over previous
#include <cuda_runtime.h>
#include <cuda_fp16.h>
#include <math.h>
#include <cstdint>

#define S_LEN 4096
#define HIDN  2048
#define NH    16
#define NKV   8
#define DH    128
#define KVW   (NKV*DH)      // 1024
#define ATT_SCALE 0.08838834764831845f   // 1/sqrt(128)

// -------- scratch (device globals: allocation-free) --------
__device__ float  g_q [(size_t)S_LEN * HIDN];   // fp32 q (pre-norm)
__device__ float  g_k [(size_t)S_LEN * KVW];    // fp32 k (pre-norm)
__device__ __half g_qh[(size_t)S_LEN * HIDN];   // fp16 q (post rms+rope)
__device__ __half g_kh[(size_t)S_LEN * KVW];    // fp16 k
__device__ __half g_vh[(size_t)S_LEN * KVW];    // fp16 v
__device__ float  g_o [(size_t)S_LEN * HIDN];   // attention output

// fp16 MMA: D(16x8,f32) += A(16x16,f16) * B(16x8,f16)
__device__ __forceinline__ void mma_h(float* d, const uint32_t* a,
                                      uint32_t b0, uint32_t b1) {
    asm volatile(
        "mma.sync.aligned.m16n8k16.row.col.f32.f16.f16.f32 "
        "{%0,%1,%2,%3}, {%4,%5,%6,%7}, {%8,%9}, {%0,%1,%2,%3};"
        : "+f"(d[0]), "+f"(d[1]), "+f"(d[2]), "+f"(d[3])
        : "r"(a[0]), "r"(a[1]), "r"(a[2]), "r"(a[3]), "r"(b0), "r"(b1));
}

// ============================================================
// GEMM: C[m][n] = sum_k A[m][k]*B[n][k] + bias[n]
// fp16 tensor path with A split (hi+lo) for near-fp32 accuracy.
// BM=BN=128, BK=32, 256 threads (8 warps 4x2), warp tile 32x64.
// ============================================================
#define APAD 40   // halfs per smem row (40*2B=80B, 20 words: conflict-free frags)

__global__ __launch_bounds__(256)
void gemm_h(const float* __restrict__ A, const float* __restrict__ B,
            const float* __restrict__ bias, float* __restrict__ C,
            __half* __restrict__ Ch, int M, int N, int K)
{
    __shared__ __half Ahs[128 * APAD];
    __shared__ __half Als[128 * APAD];
    __shared__ __half Bhs[128 * APAD];

    const int tid  = threadIdx.x;
    const int lane = tid & 31, wid = tid >> 5;
    const int g = lane >> 2, t = lane & 3;
    const int wm = wid & 3, wn = wid >> 2;
    const int bm = blockIdx.y * 128, bn = blockIdx.x * 128;
    const int lr = tid >> 3;          // 0..31
    const int lc = (tid & 7) << 2;    // 0,4,..,28

    float acc[2][8][4];
#pragma unroll
    for (int i = 0; i < 2; i++)
#pragma unroll
        for (int j = 0; j < 8; j++)
#pragma unroll
            for (int c = 0; c < 4; c++) acc[i][j][c] = 0.f;

    float4 ra[4], rb[4];

#define LOAD_TILE(k0)                                                         \
    {                                                                         \
        _Pragma("unroll")                                                     \
        for (int i = 0; i < 4; i++) {                                         \
            ra[i] = *(const float4*)(A + (size_t)(bm + lr + 32 * i) * K + (k0) + lc); \
            rb[i] = *(const float4*)(B + (size_t)(bn + lr + 32 * i) * K + (k0) + lc); \
        }                                                                     \
    }

#define STORE_TILE()                                                          \
    {                                                                         \
        _Pragma("unroll")                                                     \
        for (int i = 0; i < 4; i++) {                                         \
            const int row = lr + 32 * i;                                      \
            float4 a = ra[i];                                                 \
            __half h0 = __float2half_rn(a.x), h1 = __float2half_rn(a.y);      \
            __half h2 = __float2half_rn(a.z), h3 = __float2half_rn(a.w);      \
            __half l0 = __float2half_rn(a.x - __half2float(h0));              \
            __half l1 = __float2half_rn(a.y - __half2float(h1));              \
            __half l2 = __float2half_rn(a.z - __half2float(h2));              \
            __half l3 = __float2half_rn(a.w - __half2float(h3));              \
            __half2* ph = (__half2*)(Ahs + row * APAD + lc);                  \
            ph[0] = __halves2half2(h0, h1); ph[1] = __halves2half2(h2, h3);   \
            __half2* pl = (__half2*)(Als + row * APAD + lc);                  \
            pl[0] = __halves2half2(l0, l1); pl[1] = __halves2half2(l2, l3);   \
            float4 b = rb[i];                                                 \
            __half2* pb = (__half2*)(Bhs + row * APAD + lc);                  \
            pb[0] = __halves2half2(__float2half_rn(b.x), __float2half_rn(b.y)); \
            pb[1] = __halves2half2(__float2half_rn(b.z), __float2half_rn(b.w)); \
        }                                                                     \
    }

    LOAD_TILE(0);
    STORE_TILE();
    __syncthreads();

    const int nk = K >> 5;
    const int ab = wm * 32, bb = wn * 64;

    for (int it = 0; it < nk; ++it) {
        if (it + 1 < nk) LOAD_TILE((it + 1) << 5);

#pragma unroll
        for (int ks = 0; ks < 2; ks++) {
            const int kb = ks * 16;
            uint32_t ah[2][4], al[2][4];
#pragma unroll
            for (int i = 0; i < 2; i++) {
                const __half* p = Ahs + (ab + i * 16 + g) * APAD + kb + 2 * t;
                ah[i][0] = *(const uint32_t*)(p);
                ah[i][1] = *(const uint32_t*)(p + 8 * APAD);
                ah[i][2] = *(const uint32_t*)(p + 8);
                ah[i][3] = *(const uint32_t*)(p + 8 * APAD + 8);
                const __half* q = Als + (ab + i * 16 + g) * APAD + kb + 2 * t;
                al[i][0] = *(const uint32_t*)(q);
                al[i][1] = *(const uint32_t*)(q + 8 * APAD);
                al[i][2] = *(const uint32_t*)(q + 8);
                al[i][3] = *(const uint32_t*)(q + 8 * APAD + 8);
            }
#pragma unroll
            for (int j = 0; j < 8; j++) {
                const __half* q = Bhs + (bb + j * 8 + g) * APAD + kb + 2 * t;
                uint32_t b0 = *(const uint32_t*)(q);
                uint32_t b1 = *(const uint32_t*)(q + 8);
                mma_h(acc[0][j], ah[0], b0, b1);
                mma_h(acc[1][j], ah[1], b0, b1);
                mma_h(acc[0][j], al[0], b0, b1);
                mma_h(acc[1][j], al[1], b0, b1);
            }
        }
        __syncthreads();
        if (it + 1 < nk) {
            STORE_TILE();
            __syncthreads();
        }
    }

    // epilogue
#pragma unroll
    for (int j = 0; j < 8; j++) {
        const int col = bn + wn * 64 + j * 8 + 2 * t;
        float2 bv = make_float2(0.f, 0.f);
        if (bias) { bv.x = bias[col]; bv.y = bias[col + 1]; }
#pragma unroll
        for (int i = 0; i < 2; i++) {
            const int row = bm + wm * 32 + i * 16 + g;
            float o0 = acc[i][j][0] + bv.x, o1 = acc[i][j][1] + bv.y;
            float o2 = acc[i][j][2] + bv.x, o3 = acc[i][j][3] + bv.y;
            if (Ch) {
                *(__half2*)(Ch + (size_t)row * N + col) = __floats2half2_rn(o0, o1);
                *(__half2*)(Ch + (size_t)(row + 8) * N + col) = __floats2half2_rn(o2, o3);
            } else {
                *(float2*)(C + (size_t)row * N + col)       = make_float2(o0, o1);
                *(float2*)(C + (size_t)(row + 8) * N + col) = make_float2(o2, o3);
            }
        }
    }
#undef LOAD_TILE
#undef STORE_TILE
}

// ============================================================
// Fused RMSNorm + RoPE: fp32 in, fp16 out
// ============================================================
__global__ __launch_bounds__(128)
void rmsrope_kernel(const float* __restrict__ q, const float* __restrict__ k,
                    __half* __restrict__ qh, __half* __restrict__ kh,
                    const float* __restrict__ cosb, const float* __restrict__ sinb,
                    const float* __restrict__ qw, const float* __restrict__ kw)
{
    int s  = blockIdx.x;
    int hh = blockIdx.y;
    int d  = threadIdx.x;

    const float* base;
    __half* outp;
    const float* w;
    if (hh < NH) {
        base = q + (size_t)s * HIDN + hh * DH;
        outp = g_qh + (size_t)s * HIDN + hh * DH;
        w = qw;
    } else {
        base = k + (size_t)s * KVW + (hh - NH) * DH;
        outp = g_kh + (size_t)s * KVW + (hh - NH) * DH;
        w = kw;
    }
    (void)qh; (void)kh;

    float val = base[d];
    float ss  = val * val;
#pragma unroll
    for (int off = 16; off >= 1; off >>= 1)
        ss += __shfl_xor_sync(0xffffffffu, ss, off);

    __shared__ float red[4];
    __shared__ float sv[128];
    int lane = d & 31, wid = d >> 5;
    if (lane == 0) red[wid] = ss;
    __syncthreads();
    float tot = red[0] + red[1] + red[2] + red[3];
    float inv = rsqrtf(tot * (1.f / 128.f) + 1e-6f);

    float nv = w[d] * val * inv;
    sv[d] = nv;
    __syncthreads();
    float other = (d < 64) ? -sv[d + 64] : sv[d - 64];
    float res = nv * cosb[(size_t)s * DH + d] + other * sinb[(size_t)s * DH + d];
    outp[d] = __float2half_rn(res);
}

// ============================================================
// Flash attention, fp16 tensor cores, causal. BM=BN=64, D=128.
// 128 threads = 4 warps, warp tile 16(q) x 64(k). grid (64, 16).
// ============================================================
#define QSTR 136   // halfs per Qs/Ks row (68 words: stride%32==4, conflict-free frags)
#define VSTR 68    // halfs per Vs row (d-major / transposed V)
#define ATTN_SMEM ((64*QSTR + 64*QSTR + 128*VSTR) * 2)   // 52224 B

__global__ __launch_bounds__(128)
void attn_h(const __half* __restrict__ Q, const __half* __restrict__ K,
            const __half* __restrict__ V, float* __restrict__ O)
{
    extern __shared__ __half sh[];
    __half* Qs = sh;                 // [64][136]
    __half* Ks = Qs + 64 * QSTR;     // [64][136]
    __half* Vs = Ks + 64 * QSTR;     // [128][68]  Vs[d][k]

    const int tid  = threadIdx.x;
    const int lane = tid & 31, wid = tid >> 5;
    const int g = lane >> 2, t = lane & 3;
    const int h  = blockIdx.y;
    const int qt = (gridDim.x - 1) - blockIdx.x;   // long tiles first
    const int row0 = qt * 64;
    const int kh = h >> 1;                         // GQA reps=2
    const int row_l = wid * 16;                    // warp's local q-row base

    // load Q tile (fp16, uint4 = 8 halfs)
#pragma unroll
    for (int it = tid; it < 64 * 16; it += 128) {
        int r = it >> 4, c8 = (it & 15) << 3;
        *(uint4*)(Qs + r * QSTR + c8) =
            *(const uint4*)(Q + (size_t)(row0 + r) * HIDN + h * DH + c8);
    }

    float o[16][4];
#pragma unroll
    for (int jj = 0; jj < 16; jj++)
#pragma unroll
        for (int c = 0; c < 4; c++) o[jj][c] = 0.f;
    float m0 = -INFINITY, m1 = -INFINITY, l0 = 0.f, l1 = 0.f;

    for (int jt = 0; jt <= qt; jt++) {
        const int col0 = jt * 64;
        __syncthreads();
        // K tile
#pragma unroll
        for (int it = tid; it < 64 * 16; it += 128) {
            int r = it >> 4, c8 = (it & 15) << 3;
            *(uint4*)(Ks + r * QSTR + c8) =
                *(const uint4*)(K + (size_t)(col0 + r) * KVW + kh * DH + c8);
        }
        // V tile transposed: Vs[d][k]
#pragma unroll
        for (int it = tid; it < 64 * 128; it += 128) {
            int d = it & 127, k = it >> 7;
            Vs[d * VSTR + k] = V[(size_t)(col0 + k) * KVW + kh * DH + d];
        }
        __syncthreads();

        // ---- QK^T: S[16][64] per warp ----
        float s[8][4];
#pragma unroll
        for (int j = 0; j < 8; j++)
#pragma unroll
            for (int c = 0; c < 4; c++) s[j][c] = 0.f;

#pragma unroll
        for (int ks = 0; ks < 8; ks++) {
            const int kb = ks * 16;
            const __half* qp = Qs + (row_l + g) * QSTR + kb + 2 * t;
            uint32_t av[4];
            av[0] = *(const uint32_t*)(qp);
            av[1] = *(const uint32_t*)(qp + 8 * QSTR);
            av[2] = *(const uint32_t*)(qp + 8);
            av[3] = *(const uint32_t*)(qp + 8 * QSTR + 8);
#pragma unroll
            for (int j = 0; j < 8; j++) {
                const __half* kp = Ks + (j * 8 + g) * QSTR + kb + 2 * t;
                uint32_t b0 = *(const uint32_t*)(kp);
                uint32_t b1 = *(const uint32_t*)(kp + 8);
                mma_h(s[j], av, b0, b1);
            }
        }

        // ---- softmax (streaming) ----
        const bool diag = (jt == qt);
        const int rg = row_l + g;          // local row for c0,c1; rg+8 for c2,c3
        float mx0 = -INFINITY, mx1 = -INFINITY;
#pragma unroll
        for (int j = 0; j < 8; j++) {
            float v0 = s[j][0] * ATT_SCALE, v1 = s[j][1] * ATT_SCALE;
            float v2 = s[j][2] * ATT_SCALE, v3 = s[j][3] * ATT_SCALE;
            if (diag) {
                int c = 8 * j + 2 * t;
                if (c     > rg)     v0 = -1e30f;
                if (c + 1 > rg)     v1 = -1e30f;
                if (c     > rg + 8) v2 = -1e30f;
                if (c + 1 > rg + 8) v3 = -1e30f;
            }
            s[j][0] = v0; s[j][1] = v1; s[j][2] = v2; s[j][3] = v3;
            mx0 = fmaxf(mx0, fmaxf(v0, v1));
            mx1 = fmaxf(mx1, fmaxf(v2, v3));
        }
        mx0 = fmaxf(mx0, __shfl_xor_sync(0xffffffffu, mx0, 1));
        mx0 = fmaxf(mx0, __shfl_xor_sync(0xffffffffu, mx0, 2));
        mx1 = fmaxf(mx1, __shfl_xor_sync(0xffffffffu, mx1, 1));
        mx1 = fmaxf(mx1, __shfl_xor_sync(0xffffffffu, mx1, 2));

        const float mn0 = fmaxf(m0, mx0), mn1 = fmaxf(m1, mx1);
        const float al0 = __expf(m0 - mn0), al1 = __expf(m1 - mn1);
        float ls0 = 0.f, ls1 = 0.f;
#pragma unroll
        for (int j = 0; j < 8; j++) {
            float p0 = __expf(s[j][0] - mn0), p1 = __expf(s[j][1] - mn0);
            float p2 = __expf(s[j][2] - mn1), p3 = __expf(s[j][3] - mn1);
            s[j][0] = p0; s[j][1] = p1; s[j][2] = p2; s[j][3] = p3;
            ls0 += p0 + p1;
            ls1 += p2 + p3;
        }
        ls0 += __shfl_xor_sync(0xffffffffu, ls0, 1);
        ls0 += __shfl_xor_sync(0xffffffffu, ls0, 2);
        ls1 += __shfl_xor_sync(0xffffffffu, ls1, 1);
        ls1 += __shfl_xor_sync(0xffffffffu, ls1, 2);

        l0 = l0 * al0 + ls0;
        l1 = l1 * al1 + ls1;
        m0 = mn0; m1 = mn1;
#pragma unroll
        for (int jj = 0; jj < 16; jj++) {
            o[jj][0] *= al0; o[jj][1] *= al0;
            o[jj][2] *= al1; o[jj][3] *= al1;
        }

        // ---- PV: O[16][128] += P[16][64] * V[64][128] ----
#pragma unroll
        for (int s2 = 0; s2 < 4; s2++) {
            __half2 t0 = __floats2half2_rn(s[2 * s2][0],     s[2 * s2][1]);
            __half2 t1 = __floats2half2_rn(s[2 * s2][2],     s[2 * s2][3]);
            __half2 t2 = __floats2half2_rn(s[2 * s2 + 1][0], s[2 * s2 + 1][1]);
            __half2 t3 = __floats2half2_rn(s[2 * s2 + 1][2], s[2 * s2 + 1][3]);
            uint32_t pa[4];
            pa[0] = *(uint32_t*)&t0;
            pa[1] = *(uint32_t*)&t1;
            pa[2] = *(uint32_t*)&t2;
            pa[3] = *(uint32_t*)&t3;
            const int kb = s2 * 16;
#pragma unroll
            for (int jj = 0; jj < 16; jj++) {
                const __half* vp = Vs + (jj * 8 + g) * VSTR + kb + 2 * t;
                uint32_t b0 = *(const uint32_t*)(vp);
                uint32_t b1 = *(const uint32_t*)(vp + 8);
                mma_h(o[jj], pa, b0, b1);
            }
        }
    }

    // epilogue
    const float i0 = 1.f / l0, i1 = 1.f / l1;
    const int gr0 = row0 + row_l + g, gr1 = gr0 + 8;
#pragma unroll
    for (int jj = 0; jj < 16; jj++) {
        const int col = h * DH + jj * 8 + 2 * t;
        *(float2*)(O + (size_t)gr0 * HIDN + col) = make_float2(o[jj][0] * i0, o[jj][1] * i0);
        *(float2*)(O + (size_t)gr1 * HIDN + col) = make_float2(o[jj][2] * i1, o[jj][3] * i1);
    }
}

// ============================================================
// launch
// ============================================================
extern "C" void kernel_launch(void* const* d_in, const int* in_sizes, int n_in,
                              void* d_out, int out_size)
{
    const float* x    = (const float*)d_in[0];
    const float* cosb = (const float*)d_in[1];
    const float* sinb = (const float*)d_in[2];
    // d_in[3] = mask: ignored (exactly causal, implemented analytically)
    const float* Wq = (const float*)d_in[4];
    const float* bq = (const float*)d_in[5];
    const float* Wk = (const float*)d_in[6];
    const float* bk = (const float*)d_in[7];
    const float* Wv = (const float*)d_in[8];
    const float* bv = (const float*)d_in[9];
    const float* Wo = (const float*)d_in[10];
    const float* qw = (const float*)d_in[11];
    const float* kw = (const float*)d_in[12];
    float* out = (float*)d_out;

    float *qp, *kp, *op;
    __half *qhp, *khp, *vhp;
    cudaGetSymbolAddress((void**)&qp,  g_q);
    cudaGetSymbolAddress((void**)&kp,  g_k);
    cudaGetSymbolAddress((void**)&op,  g_o);
    cudaGetSymbolAddress((void**)&qhp, g_qh);
    cudaGetSymbolAddress((void**)&khp, g_kh);
    cudaGetSymbolAddress((void**)&vhp, g_vh);

    cudaFuncSetAttribute(attn_h, cudaFuncAttributeMaxDynamicSharedMemorySize,
                         ATTN_SMEM);

    dim3 blk(256);
    gemm_h<<<dim3(16, 32), blk>>>(x, Wq, bq, qp, nullptr, S_LEN, HIDN, HIDN);
    gemm_h<<<dim3(8, 32),  blk>>>(x, Wk, bk, kp, nullptr, S_LEN, KVW,  HIDN);
    gemm_h<<<dim3(8, 32),  blk>>>(x, Wv, bv, nullptr, vhp, S_LEN, KVW,  HIDN);

    rmsrope_kernel<<<dim3(S_LEN, NH + NKV), 128>>>(qp, kp, qhp, khp,
                                                   cosb, sinb, qw, kw);

    attn_h<<<dim3(64, NH), 128, ATTN_SMEM>>>(qhp, khp, vhp, op);

    gemm_h<<<dim3(16, 32), blk>>>(op, Wo, nullptr, out, nullptr, S_LEN, HIDN, HIDN);
}

// round 6
// speedup vs baseline: 5.0866x; 1.0803x over previous
#include <cuda_runtime.h>
#include <cuda_fp16.h>
#include <math.h>
#include <cstdint>

#define S_LEN 4096
#define HIDN  2048
#define NH    16
#define NKV   8
#define DH    128
#define KVW   (NKV*DH)      // 1024
#define ATT_SCALE 0.08838834764831845f   // 1/sqrt(128)

// -------- scratch (device globals: allocation-free) --------
__device__ float  g_q [(size_t)S_LEN * HIDN];
__device__ float  g_k [(size_t)S_LEN * KVW];
__device__ __half g_qh[(size_t)S_LEN * HIDN];
__device__ __half g_kh[(size_t)S_LEN * KVW];
__device__ __half g_vh[(size_t)S_LEN * KVW];
__device__ float  g_o [(size_t)S_LEN * HIDN];

// fp16 MMA: D(16x8,f32) += A(16x16,f16) * B(16x8,f16)
__device__ __forceinline__ void mma_h(float* d, const uint32_t* a,
                                      uint32_t b0, uint32_t b1) {
    asm volatile(
        "mma.sync.aligned.m16n8k16.row.col.f32.f16.f16.f32 "
        "{%0,%1,%2,%3}, {%4,%5,%6,%7}, {%8,%9}, {%0,%1,%2,%3};"
        : "+f"(d[0]), "+f"(d[1]), "+f"(d[2]), "+f"(d[3])
        : "r"(a[0]), "r"(a[1]), "r"(a[2]), "r"(a[3]), "r"(b0), "r"(b1));
}

__device__ __forceinline__ void ldsm_x4(uint32_t* r, uint32_t addr) {
    asm volatile("ldmatrix.sync.aligned.m8n8.x4.shared.b16 {%0,%1,%2,%3}, [%4];"
        : "=r"(r[0]), "=r"(r[1]), "=r"(r[2]), "=r"(r[3]) : "r"(addr));
}
__device__ __forceinline__ void ldsm_x4_t(uint32_t* r, uint32_t addr) {
    asm volatile("ldmatrix.sync.aligned.m8n8.x4.trans.shared.b16 {%0,%1,%2,%3}, [%4];"
        : "=r"(r[0]), "=r"(r[1]), "=r"(r[2]), "=r"(r[3]) : "r"(addr));
}

// ============================================================
// GEMM: C[m][n] = sum_k A[m][k]*B[n][k] + bias[n]
// fp16 tensor path with A split (hi+lo). ldmatrix fragment loads.
// BM=BN=128, BK=32, 256 threads (8 warps 4x2), warp tile 32x64.
// ============================================================
#define APAD 40   // halfs per smem row (80B: LDSM row-phase covers all banks)

__global__ __launch_bounds__(256)
void gemm_h(const float* __restrict__ A, const float* __restrict__ B,
            const float* __restrict__ bias, float* __restrict__ C,
            __half* __restrict__ Ch, int M, int N, int K)
{
    __shared__ __half Ahs[128 * APAD];
    __shared__ __half Als[128 * APAD];
    __shared__ __half Bhs[128 * APAD];

    const int tid  = threadIdx.x;
    const int lane = tid & 31, wid = tid >> 5;
    const int g = lane >> 2, t = lane & 3;
    const int wm = wid & 3, wn = wid >> 2;
    const int bm = blockIdx.y * 128, bn = blockIdx.x * 128;
    const int lr = tid >> 3;          // 0..31
    const int lc = (tid & 7) << 2;    // 0,4,..,28

    const int r16 = lane & 15;        // ldmatrix row within 16
    const int q8  = (lane >> 4) << 3; // 0 / 8 (k offset)

    const uint32_t sAh = (uint32_t)__cvta_generic_to_shared(Ahs);
    const uint32_t sAl = (uint32_t)__cvta_generic_to_shared(Als);
    const uint32_t sB  = (uint32_t)__cvta_generic_to_shared(Bhs);

    float acc[2][8][4];
#pragma unroll
    for (int i = 0; i < 2; i++)
#pragma unroll
        for (int j = 0; j < 8; j++)
#pragma unroll
            for (int c = 0; c < 4; c++) acc[i][j][c] = 0.f;

    float4 ra[4], rb[4];

#define LOAD_TILE(k0)                                                         \
    {                                                                         \
        _Pragma("unroll")                                                     \
        for (int i = 0; i < 4; i++) {                                         \
            ra[i] = *(const float4*)(A + (size_t)(bm + lr + 32 * i) * K + (k0) + lc); \
            rb[i] = *(const float4*)(B + (size_t)(bn + lr + 32 * i) * K + (k0) + lc); \
        }                                                                     \
    }

#define STORE_TILE()                                                          \
    {                                                                         \
        _Pragma("unroll")                                                     \
        for (int i = 0; i < 4; i++) {                                         \
            const int row = lr + 32 * i;                                      \
            float4 a = ra[i];                                                 \
            __half h0 = __float2half_rn(a.x), h1 = __float2half_rn(a.y);      \
            __half h2 = __float2half_rn(a.z), h3 = __float2half_rn(a.w);      \
            __half l0 = __float2half_rn(a.x - __half2float(h0));              \
            __half l1 = __float2half_rn(a.y - __half2float(h1));              \
            __half l2 = __float2half_rn(a.z - __half2float(h2));              \
            __half l3 = __float2half_rn(a.w - __half2float(h3));              \
            __half2* ph = (__half2*)(Ahs + row * APAD + lc);                  \
            ph[0] = __halves2half2(h0, h1); ph[1] = __halves2half2(h2, h3);   \
            __half2* pl = (__half2*)(Als + row * APAD + lc);                  \
            pl[0] = __halves2half2(l0, l1); pl[1] = __halves2half2(l2, l3);   \
            float4 b = rb[i];                                                 \
            __half2* pb = (__half2*)(Bhs + row * APAD + lc);                  \
            pb[0] = __halves2half2(__float2half_rn(b.x), __float2half_rn(b.y)); \
            pb[1] = __halves2half2(__float2half_rn(b.z), __float2half_rn(b.w)); \
        }                                                                     \
    }

    LOAD_TILE(0);
    STORE_TILE();
    __syncthreads();

    const int nk = K >> 5;
    const int ab = wm * 32, bb = wn * 64;
    // per-thread ldmatrix byte offsets (row part)
    const uint32_t aoff = (uint32_t)((ab + r16) * APAD + q8) * 2;
    const uint32_t boff = (uint32_t)((bb + r16) * APAD + q8) * 2;

    for (int it = 0; it < nk; ++it) {
        if (it + 1 < nk) LOAD_TILE((it + 1) << 5);

#pragma unroll
        for (int ks = 0; ks < 2; ks++) {
            const uint32_t kb2 = (uint32_t)(ks * 16) * 2;
            uint32_t ah[2][4], al[2][4];
#pragma unroll
            for (int i = 0; i < 2; i++) {
                ldsm_x4(ah[i], sAh + aoff + kb2 + (uint32_t)(i * 16 * APAD) * 2);
                ldsm_x4(al[i], sAl + aoff + kb2 + (uint32_t)(i * 16 * APAD) * 2);
            }
#pragma unroll
            for (int jp = 0; jp < 4; jp++) {
                uint32_t rb4[4];
                ldsm_x4(rb4, sB + boff + kb2 + (uint32_t)(jp * 16 * APAD) * 2);
                mma_h(acc[0][2 * jp],     ah[0], rb4[0], rb4[2]);
                mma_h(acc[0][2 * jp + 1], ah[0], rb4[1], rb4[3]);
                mma_h(acc[1][2 * jp],     ah[1], rb4[0], rb4[2]);
                mma_h(acc[1][2 * jp + 1], ah[1], rb4[1], rb4[3]);
                mma_h(acc[0][2 * jp],     al[0], rb4[0], rb4[2]);
                mma_h(acc[0][2 * jp + 1], al[0], rb4[1], rb4[3]);
                mma_h(acc[1][2 * jp],     al[1], rb4[0], rb4[2]);
                mma_h(acc[1][2 * jp + 1], al[1], rb4[1], rb4[3]);
            }
        }
        __syncthreads();
        if (it + 1 < nk) {
            STORE_TILE();
            __syncthreads();
        }
    }

    // epilogue
#pragma unroll
    for (int j = 0; j < 8; j++) {
        const int col = bn + wn * 64 + j * 8 + 2 * t;
        float2 bv = make_float2(0.f, 0.f);
        if (bias) { bv.x = bias[col]; bv.y = bias[col + 1]; }
#pragma unroll
        for (int i = 0; i < 2; i++) {
            const int row = bm + wm * 32 + i * 16 + g;
            float o0 = acc[i][j][0] + bv.x, o1 = acc[i][j][1] + bv.y;
            float o2 = acc[i][j][2] + bv.x, o3 = acc[i][j][3] + bv.y;
            if (Ch) {
                *(__half2*)(Ch + (size_t)row * N + col) = __floats2half2_rn(o0, o1);
                *(__half2*)(Ch + (size_t)(row + 8) * N + col) = __floats2half2_rn(o2, o3);
            } else {
                *(float2*)(C + (size_t)row * N + col)       = make_float2(o0, o1);
                *(float2*)(C + (size_t)(row + 8) * N + col) = make_float2(o2, o3);
            }
        }
    }
#undef LOAD_TILE
#undef STORE_TILE
}

// ============================================================
// Fused RMSNorm + RoPE: fp32 in, fp16 out
// ============================================================
__global__ __launch_bounds__(128)
void rmsrope_kernel(const float* __restrict__ q, const float* __restrict__ k,
                    __half* __restrict__ qh, __half* __restrict__ kh,
                    const float* __restrict__ cosb, const float* __restrict__ sinb,
                    const float* __restrict__ qw, const float* __restrict__ kw)
{
    int s  = blockIdx.x;
    int hh = blockIdx.y;
    int d  = threadIdx.x;

    const float* base;
    __half* outp;
    const float* w;
    if (hh < NH) {
        base = q + (size_t)s * HIDN + hh * DH;
        outp = qh + (size_t)s * HIDN + hh * DH;
        w = qw;
    } else {
        base = k + (size_t)s * KVW + (hh - NH) * DH;
        outp = kh + (size_t)s * KVW + (hh - NH) * DH;
        w = kw;
    }

    float val = base[d];
    float ss  = val * val;
#pragma unroll
    for (int off = 16; off >= 1; off >>= 1)
        ss += __shfl_xor_sync(0xffffffffu, ss, off);

    __shared__ float red[4];
    __shared__ float sv[128];
    int lane = d & 31, wid = d >> 5;
    if (lane == 0) red[wid] = ss;
    __syncthreads();
    float tot = red[0] + red[1] + red[2] + red[3];
    float inv = rsqrtf(tot * (1.f / 128.f) + 1e-6f);

    float nv = w[d] * val * inv;
    sv[d] = nv;
    __syncthreads();
    float other = (d < 64) ? -sv[d + 64] : sv[d - 64];
    float res = nv * cosb[(size_t)s * DH + d] + other * sinb[(size_t)s * DH + d];
    outp[d] = __float2half_rn(res);
}

// ============================================================
// Flash attention, fp16 tensor cores, causal. BM=BN=64, D=128.
// 128 threads = 4 warps, warp tile 16(q) x 64(k). grid (64, 16).
// V kept k-major; PV B-fragments via ldmatrix.trans (no transpose pass).
// ============================================================
#define QSTR 136   // halfs per row (272B: LDSM conflict-free)
#define ATTN_SMEM (3 * 64 * QSTR * 2)   // 52224 B

__global__ __launch_bounds__(128)
void attn_h(const __half* __restrict__ Q, const __half* __restrict__ K,
            const __half* __restrict__ V, float* __restrict__ O)
{
    extern __shared__ __half sh[];
    __half* Qs = sh;                 // [64][136]
    __half* Ks = Qs + 64 * QSTR;     // [64][136]
    __half* Vs = Ks + 64 * QSTR;     // [64][136]  k-major

    const int tid  = threadIdx.x;
    const int lane = tid & 31, wid = tid >> 5;
    const int g = lane >> 2, t = lane & 3;
    const int h  = blockIdx.y;
    const int qt = (gridDim.x - 1) - blockIdx.x;   // long tiles first
    const int row0 = qt * 64;
    const int kh = h >> 1;                         // GQA reps=2
    const int row_l = wid * 16;

    const int r16 = lane & 15;
    const int q8  = (lane >> 4) << 3;
    const uint32_t sQ = (uint32_t)__cvta_generic_to_shared(Qs);
    const uint32_t sK = (uint32_t)__cvta_generic_to_shared(Ks);
    const uint32_t sV = (uint32_t)__cvta_generic_to_shared(Vs);
    // ldmatrix row offsets
    const uint32_t qoff = (uint32_t)((row_l + r16) * QSTR + q8) * 2;
    const uint32_t koff = (uint32_t)(r16 * QSTR + q8) * 2;
    // trans-V lane mapping: matrix m = lane>>3, row-in-matrix ri = lane&7
    const int vm = lane >> 3, vri = lane & 7;
    const uint32_t voff =
        (uint32_t)((vri + ((vm >> 1) << 3)) * QSTR + ((vm & 1) << 3)) * 2;

    // load Q tile (uint4 = 8 halfs)
#pragma unroll
    for (int it = tid; it < 64 * 16; it += 128) {
        int r = it >> 4, c8 = (it & 15) << 3;
        *(uint4*)(Qs + r * QSTR + c8) =
            *(const uint4*)(Q + (size_t)(row0 + r) * HIDN + h * DH + c8);
    }

    float o[16][4];
#pragma unroll
    for (int jj = 0; jj < 16; jj++)
#pragma unroll
        for (int c = 0; c < 4; c++) o[jj][c] = 0.f;
    float m0 = -INFINITY, m1 = -INFINITY, l0 = 0.f, l1 = 0.f;

    for (int jt = 0; jt <= qt; jt++) {
        const int col0 = jt * 64;
        __syncthreads();
#pragma unroll
        for (int it = tid; it < 64 * 16; it += 128) {
            int r = it >> 4, c8 = (it & 15) << 3;
            *(uint4*)(Ks + r * QSTR + c8) =
                *(const uint4*)(K + (size_t)(col0 + r) * KVW + kh * DH + c8);
            *(uint4*)(Vs + r * QSTR + c8) =
                *(const uint4*)(V + (size_t)(col0 + r) * KVW + kh * DH + c8);
        }
        __syncthreads();

        // ---- QK^T: S[16][64] per warp ----
        float s[8][4];
#pragma unroll
        for (int j = 0; j < 8; j++)
#pragma unroll
            for (int c = 0; c < 4; c++) s[j][c] = 0.f;

#pragma unroll
        for (int ks = 0; ks < 8; ks++) {
            const uint32_t kb2 = (uint32_t)(ks * 16) * 2;
            uint32_t av[4];
            ldsm_x4(av, sQ + qoff + kb2);
#pragma unroll
            for (int jp = 0; jp < 4; jp++) {
                uint32_t kb4[4];
                ldsm_x4(kb4, sK + koff + kb2 + (uint32_t)(jp * 16 * QSTR) * 2);
                mma_h(s[2 * jp],     av, kb4[0], kb4[2]);
                mma_h(s[2 * jp + 1], av, kb4[1], kb4[3]);
            }
        }

        // ---- softmax (streaming) ----
        const bool diag = (jt == qt);
        const int rg = row_l + g;
        float mx0 = -INFINITY, mx1 = -INFINITY;
#pragma unroll
        for (int j = 0; j < 8; j++) {
            float v0 = s[j][0] * ATT_SCALE, v1 = s[j][1] * ATT_SCALE;
            float v2 = s[j][2] * ATT_SCALE, v3 = s[j][3] * ATT_SCALE;
            if (diag) {
                int c = 8 * j + 2 * t;
                if (c     > rg)     v0 = -1e30f;
                if (c + 1 > rg)     v1 = -1e30f;
                if (c     > rg + 8) v2 = -1e30f;
                if (c + 1 > rg + 8) v3 = -1e30f;
            }
            s[j][0] = v0; s[j][1] = v1; s[j][2] = v2; s[j][3] = v3;
            mx0 = fmaxf(mx0, fmaxf(v0, v1));
            mx1 = fmaxf(mx1, fmaxf(v2, v3));
        }
        mx0 = fmaxf(mx0, __shfl_xor_sync(0xffffffffu, mx0, 1));
        mx0 = fmaxf(mx0, __shfl_xor_sync(0xffffffffu, mx0, 2));
        mx1 = fmaxf(mx1, __shfl_xor_sync(0xffffffffu, mx1, 1));
        mx1 = fmaxf(mx1, __shfl_xor_sync(0xffffffffu, mx1, 2));

        const float mn0 = fmaxf(m0, mx0), mn1 = fmaxf(m1, mx1);
        const float al0 = __expf(m0 - mn0), al1 = __expf(m1 - mn1);
        float ls0 = 0.f, ls1 = 0.f;
#pragma unroll
        for (int j = 0; j < 8; j++) {
            float p0 = __expf(s[j][0] - mn0), p1 = __expf(s[j][1] - mn0);
            float p2 = __expf(s[j][2] - mn1), p3 = __expf(s[j][3] - mn1);
            s[j][0] = p0; s[j][1] = p1; s[j][2] = p2; s[j][3] = p3;
            ls0 += p0 + p1;
            ls1 += p2 + p3;
        }
        ls0 += __shfl_xor_sync(0xffffffffu, ls0, 1);
        ls0 += __shfl_xor_sync(0xffffffffu, ls0, 2);
        ls1 += __shfl_xor_sync(0xffffffffu, ls1, 1);
        ls1 += __shfl_xor_sync(0xffffffffu, ls1, 2);

        l0 = l0 * al0 + ls0;
        l1 = l1 * al1 + ls1;
        m0 = mn0; m1 = mn1;
#pragma unroll
        for (int jj = 0; jj < 16; jj++) {
            o[jj][0] *= al0; o[jj][1] *= al0;
            o[jj][2] *= al1; o[jj][3] *= al1;
        }

        // ---- PV: O[16][128] += P[16][64] * V[64][128] ----
#pragma unroll
        for (int s2 = 0; s2 < 4; s2++) {
            __half2 t0 = __floats2half2_rn(s[2 * s2][0],     s[2 * s2][1]);
            __half2 t1 = __floats2half2_rn(s[2 * s2][2],     s[2 * s2][3]);
            __half2 t2 = __floats2half2_rn(s[2 * s2 + 1][0], s[2 * s2 + 1][1]);
            __half2 t3 = __floats2half2_rn(s[2 * s2 + 1][2], s[2 * s2 + 1][3]);
            uint32_t pa[4];
            pa[0] = *(uint32_t*)&t0;
            pa[1] = *(uint32_t*)&t1;
            pa[2] = *(uint32_t*)&t2;
            pa[3] = *(uint32_t*)&t3;
            const uint32_t vrow2 = (uint32_t)(s2 * 16 * QSTR) * 2;
#pragma unroll
            for (int djp = 0; djp < 8; djp++) {
                uint32_t vb[4];
                ldsm_x4_t(vb, sV + voff + vrow2 + (uint32_t)(djp * 16) * 2);
                mma_h(o[2 * djp],     pa, vb[0], vb[2]);
                mma_h(o[2 * djp + 1], pa, vb[1], vb[3]);
            }
        }
    }

    // epilogue
    const float i0 = 1.f / l0, i1 = 1.f / l1;
    const int gr0 = row0 + row_l + g, gr1 = gr0 + 8;
#pragma unroll
    for (int jj = 0; jj < 16; jj++) {
        const int col = h * DH + jj * 8 + 2 * t;
        *(float2*)(O + (size_t)gr0 * HIDN + col) = make_float2(o[jj][0] * i0, o[jj][1] * i0);
        *(float2*)(O + (size_t)gr1 * HIDN + col) = make_float2(o[jj][2] * i1, o[jj][3] * i1);
    }
}

// ============================================================
// launch
// ============================================================
extern "C" void kernel_launch(void* const* d_in, const int* in_sizes, int n_in,
                              void* d_out, int out_size)
{
    const float* x    = (const float*)d_in[0];
    const float* cosb = (const float*)d_in[1];
    const float* sinb = (const float*)d_in[2];
    // d_in[3] = mask: ignored (exactly causal, implemented analytically)
    const float* Wq = (const float*)d_in[4];
    const float* bq = (const float*)d_in[5];
    const float* Wk = (const float*)d_in[6];
    const float* bk = (const float*)d_in[7];
    const float* Wv = (const float*)d_in[8];
    const float* bv = (const float*)d_in[9];
    const float* Wo = (const float*)d_in[10];
    const float* qw = (const float*)d_in[11];
    const float* kw = (const float*)d_in[12];
    float* out = (float*)d_out;

    float *qp, *kp, *op;
    __half *qhp, *khp, *vhp;
    cudaGetSymbolAddress((void**)&qp,  g_q);
    cudaGetSymbolAddress((void**)&kp,  g_k);
    cudaGetSymbolAddress((void**)&op,  g_o);
    cudaGetSymbolAddress((void**)&qhp, g_qh);
    cudaGetSymbolAddress((void**)&khp, g_kh);
    cudaGetSymbolAddress((void**)&vhp, g_vh);

    cudaFuncSetAttribute(attn_h, cudaFuncAttributeMaxDynamicSharedMemorySize,
                         ATTN_SMEM);

    dim3 blk(256);
    gemm_h<<<dim3(16, 32), blk>>>(x, Wq, bq, qp, nullptr, S_LEN, HIDN, HIDN);
    gemm_h<<<dim3(8, 32),  blk>>>(x, Wk, bk, kp, nullptr, S_LEN, KVW,  HIDN);
    gemm_h<<<dim3(8, 32),  blk>>>(x, Wv, bv, nullptr, vhp, S_LEN, KVW,  HIDN);

    rmsrope_kernel<<<dim3(S_LEN, NH + NKV), 128>>>(qp, kp, qhp, khp,
                                                   cosb, sinb, qw, kw);

    attn_h<<<dim3(64, NH), 128, ATTN_SMEM>>>(qhp, khp, vhp, op);

    gemm_h<<<dim3(16, 32), blk>>>(op, Wo, nullptr, out, nullptr, S_LEN, HIDN, HIDN);
}

// round 7
// speedup vs baseline: 5.5442x; 1.0900x over previous
#include <cuda_runtime.h>
#include <cuda_fp16.h>
#include <math.h>
#include <cstdint>

#define S_LEN 4096
#define HIDN  2048
#define NH    16
#define NKV   8
#define DH    128
#define KVW   (NKV*DH)      // 1024
#define ATT_SCALE 0.08838834764831845f   // 1/sqrt(128)

// -------- scratch (device globals: allocation-free) --------
__device__ float  g_q [(size_t)S_LEN * HIDN];
__device__ float  g_k [(size_t)S_LEN * KVW];
__device__ __half g_qh[(size_t)S_LEN * HIDN];
__device__ __half g_kh[(size_t)S_LEN * KVW];
__device__ __half g_vh[(size_t)S_LEN * KVW];
__device__ float  g_o [(size_t)S_LEN * HIDN];

// fp16 MMA: D(16x8,f32) += A(16x16,f16) * B(16x8,f16)
__device__ __forceinline__ void mma_h(float* d, const uint32_t* a,
                                      uint32_t b0, uint32_t b1) {
    asm volatile(
        "mma.sync.aligned.m16n8k16.row.col.f32.f16.f16.f32 "
        "{%0,%1,%2,%3}, {%4,%5,%6,%7}, {%8,%9}, {%0,%1,%2,%3};"
        : "+f"(d[0]), "+f"(d[1]), "+f"(d[2]), "+f"(d[3])
        : "r"(a[0]), "r"(a[1]), "r"(a[2]), "r"(a[3]), "r"(b0), "r"(b1));
}

__device__ __forceinline__ void ldsm_x4(uint32_t* r, uint32_t addr) {
    asm volatile("ldmatrix.sync.aligned.m8n8.x4.shared.b16 {%0,%1,%2,%3}, [%4];"
        : "=r"(r[0]), "=r"(r[1]), "=r"(r[2]), "=r"(r[3]) : "r"(addr));
}
__device__ __forceinline__ void ldsm_x4_t(uint32_t* r, uint32_t addr) {
    asm volatile("ldmatrix.sync.aligned.m8n8.x4.trans.shared.b16 {%0,%1,%2,%3}, [%4];"
        : "=r"(r[0]), "=r"(r[1]), "=r"(r[2]), "=r"(r[3]) : "r"(addr));
}

// ============================================================
// GEMM: C[m][n] = sum_k A[m][k]*B[n][k] + bias[n]
// fp16 tensor path; optional A hi/lo split (SPLIT=true) for accuracy.
// BM=BN=128, BK=32, 256 threads (8 warps 4x2), warp tile 32x64.
// ============================================================
#define APAD 40

template<bool SPLIT>
__global__ __launch_bounds__(256)
void gemm_h(const float* __restrict__ A, const float* __restrict__ B,
            const float* __restrict__ bias, float* __restrict__ C,
            __half* __restrict__ Ch, int M, int N, int K)
{
    __shared__ __half Ahs[128 * APAD];
    __shared__ __half Als[128 * APAD];
    __shared__ __half Bhs[128 * APAD];

    const int tid  = threadIdx.x;
    const int lane = tid & 31, wid = tid >> 5;
    const int g = lane >> 2, t = lane & 3;
    const int wm = wid & 3, wn = wid >> 2;
    const int bm = blockIdx.y * 128, bn = blockIdx.x * 128;
    const int lr = tid >> 3;
    const int lc = (tid & 7) << 2;

    const int r16 = lane & 15;
    const int q8  = (lane >> 4) << 3;

    const uint32_t sAh = (uint32_t)__cvta_generic_to_shared(Ahs);
    const uint32_t sAl = (uint32_t)__cvta_generic_to_shared(Als);
    const uint32_t sB  = (uint32_t)__cvta_generic_to_shared(Bhs);

    float acc[2][8][4];
#pragma unroll
    for (int i = 0; i < 2; i++)
#pragma unroll
        for (int j = 0; j < 8; j++)
#pragma unroll
            for (int c = 0; c < 4; c++) acc[i][j][c] = 0.f;

    float4 ra[4], rb[4];

#define LOAD_TILE(k0)                                                         \
    {                                                                         \
        _Pragma("unroll")                                                     \
        for (int i = 0; i < 4; i++) {                                         \
            ra[i] = *(const float4*)(A + (size_t)(bm + lr + 32 * i) * K + (k0) + lc); \
            rb[i] = *(const float4*)(B + (size_t)(bn + lr + 32 * i) * K + (k0) + lc); \
        }                                                                     \
    }

#define STORE_TILE()                                                          \
    {                                                                         \
        _Pragma("unroll")                                                     \
        for (int i = 0; i < 4; i++) {                                         \
            const int row = lr + 32 * i;                                      \
            float4 a = ra[i];                                                 \
            __half h0 = __float2half_rn(a.x), h1 = __float2half_rn(a.y);      \
            __half h2 = __float2half_rn(a.z), h3 = __float2half_rn(a.w);      \
            __half2* ph = (__half2*)(Ahs + row * APAD + lc);                  \
            ph[0] = __halves2half2(h0, h1); ph[1] = __halves2half2(h2, h3);   \
            if (SPLIT) {                                                      \
                __half l0 = __float2half_rn(a.x - __half2float(h0));          \
                __half l1 = __float2half_rn(a.y - __half2float(h1));          \
                __half l2 = __float2half_rn(a.z - __half2float(h2));          \
                __half l3 = __float2half_rn(a.w - __half2float(h3));          \
                __half2* pl = (__half2*)(Als + row * APAD + lc);              \
                pl[0] = __halves2half2(l0, l1); pl[1] = __halves2half2(l2, l3); \
            }                                                                 \
            float4 b = rb[i];                                                 \
            __half2* pb = (__half2*)(Bhs + row * APAD + lc);                  \
            pb[0] = __halves2half2(__float2half_rn(b.x), __float2half_rn(b.y)); \
            pb[1] = __halves2half2(__float2half_rn(b.z), __float2half_rn(b.w)); \
        }                                                                     \
    }

    LOAD_TILE(0);
    STORE_TILE();
    __syncthreads();

    const int nk = K >> 5;
    const int ab = wm * 32, bb = wn * 64;
    const uint32_t aoff = (uint32_t)((ab + r16) * APAD + q8) * 2;
    const uint32_t boff = (uint32_t)((bb + r16) * APAD + q8) * 2;

    for (int it = 0; it < nk; ++it) {
        if (it + 1 < nk) LOAD_TILE((it + 1) << 5);

#pragma unroll
        for (int ks = 0; ks < 2; ks++) {
            const uint32_t kb2 = (uint32_t)(ks * 16) * 2;
            uint32_t ah[2][4], al[2][4];
#pragma unroll
            for (int i = 0; i < 2; i++) {
                ldsm_x4(ah[i], sAh + aoff + kb2 + (uint32_t)(i * 16 * APAD) * 2);
                if (SPLIT)
                    ldsm_x4(al[i], sAl + aoff + kb2 + (uint32_t)(i * 16 * APAD) * 2);
            }
#pragma unroll
            for (int jp = 0; jp < 4; jp++) {
                uint32_t rb4[4];
                ldsm_x4(rb4, sB + boff + kb2 + (uint32_t)(jp * 16 * APAD) * 2);
                mma_h(acc[0][2 * jp],     ah[0], rb4[0], rb4[2]);
                mma_h(acc[0][2 * jp + 1], ah[0], rb4[1], rb4[3]);
                mma_h(acc[1][2 * jp],     ah[1], rb4[0], rb4[2]);
                mma_h(acc[1][2 * jp + 1], ah[1], rb4[1], rb4[3]);
                if (SPLIT) {
                    mma_h(acc[0][2 * jp],     al[0], rb4[0], rb4[2]);
                    mma_h(acc[0][2 * jp + 1], al[0], rb4[1], rb4[3]);
                    mma_h(acc[1][2 * jp],     al[1], rb4[0], rb4[2]);
                    mma_h(acc[1][2 * jp + 1], al[1], rb4[1], rb4[3]);
                }
            }
        }
        __syncthreads();
        if (it + 1 < nk) {
            STORE_TILE();
            __syncthreads();
        }
    }

    // epilogue
#pragma unroll
    for (int j = 0; j < 8; j++) {
        const int col = bn + wn * 64 + j * 8 + 2 * t;
        float2 bv = make_float2(0.f, 0.f);
        if (bias) { bv.x = bias[col]; bv.y = bias[col + 1]; }
#pragma unroll
        for (int i = 0; i < 2; i++) {
            const int row = bm + wm * 32 + i * 16 + g;
            float o0 = acc[i][j][0] + bv.x, o1 = acc[i][j][1] + bv.y;
            float o2 = acc[i][j][2] + bv.x, o3 = acc[i][j][3] + bv.y;
            if (Ch) {
                *(__half2*)(Ch + (size_t)row * N + col) = __floats2half2_rn(o0, o1);
                *(__half2*)(Ch + (size_t)(row + 8) * N + col) = __floats2half2_rn(o2, o3);
            } else {
                *(float2*)(C + (size_t)row * N + col)       = make_float2(o0, o1);
                *(float2*)(C + (size_t)(row + 8) * N + col) = make_float2(o2, o3);
            }
        }
    }
#undef LOAD_TILE
#undef STORE_TILE
}

// ============================================================
// Fused RMSNorm + RoPE: fp32 in, fp16 out
// ============================================================
__global__ __launch_bounds__(128)
void rmsrope_kernel(const float* __restrict__ q, const float* __restrict__ k,
                    __half* __restrict__ qh, __half* __restrict__ kh,
                    const float* __restrict__ cosb, const float* __restrict__ sinb,
                    const float* __restrict__ qw, const float* __restrict__ kw)
{
    int s  = blockIdx.x;
    int hh = blockIdx.y;
    int d  = threadIdx.x;

    const float* base;
    __half* outp;
    const float* w;
    if (hh < NH) {
        base = q + (size_t)s * HIDN + hh * DH;
        outp = qh + (size_t)s * HIDN + hh * DH;
        w = qw;
    } else {
        base = k + (size_t)s * KVW + (hh - NH) * DH;
        outp = kh + (size_t)s * KVW + (hh - NH) * DH;
        w = kw;
    }

    float val = base[d];
    float ss  = val * val;
#pragma unroll
    for (int off = 16; off >= 1; off >>= 1)
        ss += __shfl_xor_sync(0xffffffffu, ss, off);

    __shared__ float red[4];
    __shared__ float sv[128];
    int lane = d & 31, wid = d >> 5;
    if (lane == 0) red[wid] = ss;
    __syncthreads();
    float tot = red[0] + red[1] + red[2] + red[3];
    float inv = rsqrtf(tot * (1.f / 128.f) + 1e-6f);

    float nv = w[d] * val * inv;
    sv[d] = nv;
    __syncthreads();
    float other = (d < 64) ? -sv[d + 64] : sv[d - 64];
    float res = nv * cosb[(size_t)s * DH + d] + other * sinb[(size_t)s * DH + d];
    outp[d] = __float2half_rn(res);
}

// ============================================================
// Flash attention, fp16 tensor cores, causal. BM=128, BN=64, D=128.
// 256 threads = 8 warps, each warp 16 q-rows. grid (32, 16).
// ============================================================
#define QSTR 136
#define ATTN_SMEM ((128 * QSTR + 2 * 64 * QSTR) * 2)   // 69632 B

__global__ __launch_bounds__(256)
void attn_h(const __half* __restrict__ Q, const __half* __restrict__ K,
            const __half* __restrict__ V, float* __restrict__ O)
{
    extern __shared__ __half sh[];
    __half* Qs = sh;                  // [128][136]
    __half* Ks = Qs + 128 * QSTR;     // [64][136]
    __half* Vs = Ks + 64 * QSTR;      // [64][136]  k-major

    const int tid  = threadIdx.x;
    const int lane = tid & 31, wid = tid >> 5;
    const int g = lane >> 2, t = lane & 3;
    const int h  = blockIdx.y;
    const int tq = (gridDim.x - 1) - blockIdx.x;   // long tiles first
    const int row0 = tq * 128;
    const int kh = h >> 1;                         // GQA reps=2
    const int row_l = wid * 16;

    const int r16 = lane & 15;
    const int q8  = (lane >> 4) << 3;
    const uint32_t sQ = (uint32_t)__cvta_generic_to_shared(Qs);
    const uint32_t sK = (uint32_t)__cvta_generic_to_shared(Ks);
    const uint32_t sV = (uint32_t)__cvta_generic_to_shared(Vs);
    const uint32_t qoff = (uint32_t)((row_l + r16) * QSTR + q8) * 2;
    const uint32_t koff = (uint32_t)(r16 * QSTR + q8) * 2;
    const int vm = lane >> 3, vri = lane & 7;
    const uint32_t voff =
        (uint32_t)((vri + ((vm >> 1) << 3)) * QSTR + ((vm & 1) << 3)) * 2;

    // load Q tile: 128 rows x 16 uint4
#pragma unroll
    for (int it = tid; it < 128 * 16; it += 256) {
        int r = it >> 4, c8 = (it & 15) << 3;
        *(uint4*)(Qs + r * QSTR + c8) =
            *(const uint4*)(Q + (size_t)(row0 + r) * HIDN + h * DH + c8);
    }

    float o[16][4];
#pragma unroll
    for (int jj = 0; jj < 16; jj++)
#pragma unroll
        for (int c = 0; c < 4; c++) o[jj][c] = 0.f;
    float m0 = -INFINITY, m1 = -INFINITY, l0 = 0.f, l1 = 0.f;

    const int njt = 2 * tq + 2;
    for (int jt = 0; jt < njt; jt++) {
        const int col0 = jt * 64;
        __syncthreads();
#pragma unroll
        for (int it = tid; it < 64 * 16; it += 256) {
            int r = it >> 4, c8 = (it & 15) << 3;
            *(uint4*)(Ks + r * QSTR + c8) =
                *(const uint4*)(K + (size_t)(col0 + r) * KVW + kh * DH + c8);
            *(uint4*)(Vs + r * QSTR + c8) =
                *(const uint4*)(V + (size_t)(col0 + r) * KVW + kh * DH + c8);
        }
        __syncthreads();

        // warps whose rows are entirely above this kv tile: skip compute
        if (jt == 2 * tq + 1 && wid < 4) continue;

        // ---- QK^T: S[16][64] per warp ----
        float s[8][4];
#pragma unroll
        for (int j = 0; j < 8; j++)
#pragma unroll
            for (int c = 0; c < 4; c++) s[j][c] = 0.f;

#pragma unroll
        for (int ks = 0; ks < 8; ks++) {
            const uint32_t kb2 = (uint32_t)(ks * 16) * 2;
            uint32_t av[4];
            ldsm_x4(av, sQ + qoff + kb2);
#pragma unroll
            for (int jp = 0; jp < 4; jp++) {
                uint32_t kb4[4];
                ldsm_x4(kb4, sK + koff + kb2 + (uint32_t)(jp * 16 * QSTR) * 2);
                mma_h(s[2 * jp],     av, kb4[0], kb4[2]);
                mma_h(s[2 * jp + 1], av, kb4[1], kb4[3]);
            }
        }

        // ---- softmax (streaming) ----
        const bool diag = (jt >= 2 * tq);
        const int crel = (jt - 2 * tq) * 64;     // col offset rel. to row0
        const int rg = row_l + g;
        float mx0 = -INFINITY, mx1 = -INFINITY;
#pragma unroll
        for (int j = 0; j < 8; j++) {
            float v0 = s[j][0] * ATT_SCALE, v1 = s[j][1] * ATT_SCALE;
            float v2 = s[j][2] * ATT_SCALE, v3 = s[j][3] * ATT_SCALE;
            if (diag) {
                int c = crel + 8 * j + 2 * t;
                if (c     > rg)     v0 = -1e30f;
                if (c + 1 > rg)     v1 = -1e30f;
                if (c     > rg + 8) v2 = -1e30f;
                if (c + 1 > rg + 8) v3 = -1e30f;
            }
            s[j][0] = v0; s[j][1] = v1; s[j][2] = v2; s[j][3] = v3;
            mx0 = fmaxf(mx0, fmaxf(v0, v1));
            mx1 = fmaxf(mx1, fmaxf(v2, v3));
        }
        mx0 = fmaxf(mx0, __shfl_xor_sync(0xffffffffu, mx0, 1));
        mx0 = fmaxf(mx0, __shfl_xor_sync(0xffffffffu, mx0, 2));
        mx1 = fmaxf(mx1, __shfl_xor_sync(0xffffffffu, mx1, 1));
        mx1 = fmaxf(mx1, __shfl_xor_sync(0xffffffffu, mx1, 2));

        const float mn0 = fmaxf(m0, mx0), mn1 = fmaxf(m1, mx1);
        const float al0 = __expf(m0 - mn0), al1 = __expf(m1 - mn1);
        float ls0 = 0.f, ls1 = 0.f;
#pragma unroll
        for (int j = 0; j < 8; j++) {
            float p0 = __expf(s[j][0] - mn0), p1 = __expf(s[j][1] - mn0);
            float p2 = __expf(s[j][2] - mn1), p3 = __expf(s[j][3] - mn1);
            s[j][0] = p0; s[j][1] = p1; s[j][2] = p2; s[j][3] = p3;
            ls0 += p0 + p1;
            ls1 += p2 + p3;
        }
        ls0 += __shfl_xor_sync(0xffffffffu, ls0, 1);
        ls0 += __shfl_xor_sync(0xffffffffu, ls0, 2);
        ls1 += __shfl_xor_sync(0xffffffffu, ls1, 1);
        ls1 += __shfl_xor_sync(0xffffffffu, ls1, 2);

        l0 = l0 * al0 + ls0;
        l1 = l1 * al1 + ls1;
        m0 = mn0; m1 = mn1;
#pragma unroll
        for (int jj = 0; jj < 16; jj++) {
            o[jj][0] *= al0; o[jj][1] *= al0;
            o[jj][2] *= al1; o[jj][3] *= al1;
        }

        // ---- PV ----
#pragma unroll
        for (int s2 = 0; s2 < 4; s2++) {
            __half2 t0 = __floats2half2_rn(s[2 * s2][0],     s[2 * s2][1]);
            __half2 t1 = __floats2half2_rn(s[2 * s2][2],     s[2 * s2][3]);
            __half2 t2 = __floats2half2_rn(s[2 * s2 + 1][0], s[2 * s2 + 1][1]);
            __half2 t3 = __floats2half2_rn(s[2 * s2 + 1][2], s[2 * s2 + 1][3]);
            uint32_t pa[4];
            pa[0] = *(uint32_t*)&t0;
            pa[1] = *(uint32_t*)&t1;
            pa[2] = *(uint32_t*)&t2;
            pa[3] = *(uint32_t*)&t3;
            const uint32_t vrow2 = (uint32_t)(s2 * 16 * QSTR) * 2;
#pragma unroll
            for (int djp = 0; djp < 8; djp++) {
                uint32_t vb[4];
                ldsm_x4_t(vb, sV + voff + vrow2 + (uint32_t)(djp * 16) * 2);
                mma_h(o[2 * djp],     pa, vb[0], vb[2]);
                mma_h(o[2 * djp + 1], pa, vb[1], vb[3]);
            }
        }
    }

    // epilogue
    const float i0 = 1.f / l0, i1 = 1.f / l1;
    const int gr0 = row0 + row_l + g, gr1 = gr0 + 8;
#pragma unroll
    for (int jj = 0; jj < 16; jj++) {
        const int col = h * DH + jj * 8 + 2 * t;
        *(float2*)(O + (size_t)gr0 * HIDN + col) = make_float2(o[jj][0] * i0, o[jj][1] * i0);
        *(float2*)(O + (size_t)gr1 * HIDN + col) = make_float2(o[jj][2] * i1, o[jj][3] * i1);
    }
}

// ============================================================
// launch
// ============================================================
extern "C" void kernel_launch(void* const* d_in, const int* in_sizes, int n_in,
                              void* d_out, int out_size)
{
    const float* x    = (const float*)d_in[0];
    const float* cosb = (const float*)d_in[1];
    const float* sinb = (const float*)d_in[2];
    // d_in[3] = mask: ignored (exactly causal, implemented analytically)
    const float* Wq = (const float*)d_in[4];
    const float* bq = (const float*)d_in[5];
    const float* Wk = (const float*)d_in[6];
    const float* bk = (const float*)d_in[7];
    const float* Wv = (const float*)d_in[8];
    const float* bv = (const float*)d_in[9];
    const float* Wo = (const float*)d_in[10];
    const float* qw = (const float*)d_in[11];
    const float* kw = (const float*)d_in[12];
    float* out = (float*)d_out;

    float *qp, *kp, *op;
    __half *qhp, *khp, *vhp;
    cudaGetSymbolAddress((void**)&qp,  g_q);
    cudaGetSymbolAddress((void**)&kp,  g_k);
    cudaGetSymbolAddress((void**)&op,  g_o);
    cudaGetSymbolAddress((void**)&qhp, g_qh);
    cudaGetSymbolAddress((void**)&khp, g_kh);
    cudaGetSymbolAddress((void**)&vhp, g_vh);

    cudaFuncSetAttribute(attn_h, cudaFuncAttributeMaxDynamicSharedMemorySize,
                         ATTN_SMEM);

    dim3 blk(256);
    // Q/K/V projections: plain fp16 (outputs get rounded to fp16 anyway)
    gemm_h<false><<<dim3(16, 32), blk>>>(x, Wq, bq, qp, nullptr, S_LEN, HIDN, HIDN);
    gemm_h<false><<<dim3(8, 32),  blk>>>(x, Wk, bk, kp, nullptr, S_LEN, KVW,  HIDN);
    gemm_h<false><<<dim3(8, 32),  blk>>>(x, Wv, bv, nullptr, vhp, S_LEN, KVW,  HIDN);

    rmsrope_kernel<<<dim3(S_LEN, NH + NKV), 128>>>(qp, kp, qhp, khp,
                                                   cosb, sinb, qw, kw);

    attn_h<<<dim3(32, NH), 256, ATTN_SMEM>>>(qhp, khp, vhp, op);

    // O projection: split-A (hi+lo) for near-fp32 accuracy into final output
    gemm_h<true><<<dim3(16, 32), blk>>>(op, Wo, nullptr, out, nullptr, S_LEN, HIDN, HIDN);
}

// round 8
// speedup vs baseline: 6.5249x; 1.1769x over previous
#include <cuda_runtime.h>
#include <cuda_fp16.h>
#include <math.h>
#include <cstdint>

#define S_LEN 4096
#define HIDN  2048
#define NH    16
#define NKV   8
#define DH    128
#define KVW   (NKV*DH)      // 1024
#define ATT_SCALE 0.08838834764831845f   // 1/sqrt(128)

// -------- scratch (device globals: allocation-free) --------
__device__ float  g_q  [(size_t)S_LEN * HIDN];   // fp32 q (pre-norm)
__device__ float  g_k  [(size_t)S_LEN * KVW];    // fp32 k (pre-norm)
__device__ __half g_xh [(size_t)S_LEN * HIDN];   // fp16 x
__device__ __half g_wq [(size_t)HIDN * HIDN];
__device__ __half g_wk [(size_t)KVW  * HIDN];
__device__ __half g_wv [(size_t)KVW  * HIDN];
__device__ __half g_wo [(size_t)HIDN * HIDN];
__device__ __half g_qh [(size_t)S_LEN * HIDN];
__device__ __half g_kh [(size_t)S_LEN * KVW];
__device__ __half g_vh [(size_t)S_LEN * KVW];
__device__ __half g_ohi[(size_t)S_LEN * HIDN];   // attn out hi
__device__ __half g_olo[(size_t)S_LEN * HIDN];   // attn out lo

// ---------------- PTX helpers ----------------
__device__ __forceinline__ void mma_h(float* d, const uint32_t* a,
                                      uint32_t b0, uint32_t b1) {
    asm volatile(
        "mma.sync.aligned.m16n8k16.row.col.f32.f16.f16.f32 "
        "{%0,%1,%2,%3}, {%4,%5,%6,%7}, {%8,%9}, {%0,%1,%2,%3};"
        : "+f"(d[0]), "+f"(d[1]), "+f"(d[2]), "+f"(d[3])
        : "r"(a[0]), "r"(a[1]), "r"(a[2]), "r"(a[3]), "r"(b0), "r"(b1));
}
__device__ __forceinline__ void ldsm_x4(uint32_t* r, uint32_t addr) {
    asm volatile("ldmatrix.sync.aligned.m8n8.x4.shared.b16 {%0,%1,%2,%3}, [%4];"
        : "=r"(r[0]), "=r"(r[1]), "=r"(r[2]), "=r"(r[3]) : "r"(addr));
}
__device__ __forceinline__ void ldsm_x4_t(uint32_t* r, uint32_t addr) {
    asm volatile("ldmatrix.sync.aligned.m8n8.x4.trans.shared.b16 {%0,%1,%2,%3}, [%4];"
        : "=r"(r[0]), "=r"(r[1]), "=r"(r[2]), "=r"(r[3]) : "r"(addr));
}
__device__ __forceinline__ void cp16(uint32_t dst, const void* src) {
    asm volatile("cp.async.cg.shared.global [%0], [%1], 16;" :: "r"(dst), "l"(src));
}
#define CP_COMMIT() asm volatile("cp.async.commit_group;" ::: "memory")
#define CP_WAIT(n)  asm volatile("cp.async.wait_group %0;" :: "n"(n) : "memory")

// ============================================================
// fp32 -> fp16 conversion (grid-stride, float4)
// ============================================================
__global__ __launch_bounds__(256)
void f2h_kernel(const float4* __restrict__ src, __half2* __restrict__ dst, int n4)
{
    int i = blockIdx.x * blockDim.x + threadIdx.x;
    if (i < n4) {
        float4 v = src[i];
        dst[2 * i]     = __floats2half2_rn(v.x, v.y);
        dst[2 * i + 1] = __floats2half2_rn(v.z, v.w);
    }
}

// ============================================================
// GEMM (all-fp16 operands, cp.async 3-stage pipeline):
// C[m][n] = sum_k A[m][k]*B[n][k] (+ lo-part if SPLIT) + bias[n]
// BM=BN=128, BK=32, 256 threads (8 warps 4x2), warp tile 32x64.
// ============================================================
#define APAD 40
#define G_AS   (128 * APAD)          // halfs per A (or B) stage matrix
#define G_ASB  (G_AS * 2)            // bytes

template<bool SPLIT>
__global__ __launch_bounds__(256)
void gemm_a(const __half* __restrict__ Ah, const __half* __restrict__ Al,
            const __half* __restrict__ Bh, const float* __restrict__ bias,
            float* __restrict__ C, __half* __restrict__ Ch,
            int M, int N, int K)
{
    extern __shared__ __half sm[];
    const uint32_t sbase = (uint32_t)__cvta_generic_to_shared(sm);
    const uint32_t stageB = (SPLIT ? 3 : 2) * G_ASB;

    const int tid  = threadIdx.x;
    const int lane = tid & 31, wid = tid >> 5;
    const int g = lane >> 2, t = lane & 3;
    const int wm = wid & 3, wn = wid >> 2;
    const int bm = blockIdx.y * 128, bn = blockIdx.x * 128;
    const int r16 = lane & 15;
    const int q8  = (lane >> 4) << 3;

    float acc[2][8][4];
#pragma unroll
    for (int i = 0; i < 2; i++)
#pragma unroll
        for (int j = 0; j < 8; j++)
#pragma unroll
            for (int c = 0; c < 4; c++) acc[i][j][c] = 0.f;

    // cp.async issue of one k-tile into stage s
    auto issue = [&](int k0, int s) {
        const uint32_t sa = sbase + (uint32_t)s * stageB;
#pragma unroll
        for (int i = 0; i < 2; i++) {
            int idx = tid + (i << 8);
            int row = idx >> 2, c8 = (idx & 3) << 3;
            uint32_t off = (uint32_t)(row * APAD + c8) * 2;
            cp16(sa + off,          Ah + (size_t)(bm + row) * K + k0 + c8);
            cp16(sa + G_ASB + off,  Bh + (size_t)(bn + row) * K + k0 + c8);
            if (SPLIT)
                cp16(sa + 2 * G_ASB + off, Al + (size_t)(bm + row) * K + k0 + c8);
        }
        CP_COMMIT();
    };

    const int nk = K >> 5;
    issue(0, 0);
    issue(32, 1);

    const int ab = wm * 32, bb = wn * 64;
    const uint32_t aoff = (uint32_t)((ab + r16) * APAD + q8) * 2;
    const uint32_t boff = (uint32_t)((bb + r16) * APAD + q8) * 2;

    for (int it = 0; it < nk; ++it) {
        if (it < nk - 1) CP_WAIT(1); else CP_WAIT(0);
        __syncthreads();
        if (it + 2 < nk) issue((it + 2) << 5, (it + 2) % 3);

        const uint32_t sA  = sbase + (uint32_t)(it % 3) * stageB;
        const uint32_t sB  = sA + G_ASB;
        const uint32_t sAl = sA + 2 * G_ASB;

#pragma unroll
        for (int ks = 0; ks < 2; ks++) {
            const uint32_t kb2 = (uint32_t)(ks * 16) * 2;
            uint32_t ah[2][4], al[2][4];
#pragma unroll
            for (int i = 0; i < 2; i++) {
                ldsm_x4(ah[i], sA + aoff + kb2 + (uint32_t)(i * 16 * APAD) * 2);
                if (SPLIT)
                    ldsm_x4(al[i], sAl + aoff + kb2 + (uint32_t)(i * 16 * APAD) * 2);
            }
#pragma unroll
            for (int jp = 0; jp < 4; jp++) {
                uint32_t rb4[4];
                ldsm_x4(rb4, sB + boff + kb2 + (uint32_t)(jp * 16 * APAD) * 2);
                mma_h(acc[0][2 * jp],     ah[0], rb4[0], rb4[2]);
                mma_h(acc[0][2 * jp + 1], ah[0], rb4[1], rb4[3]);
                mma_h(acc[1][2 * jp],     ah[1], rb4[0], rb4[2]);
                mma_h(acc[1][2 * jp + 1], ah[1], rb4[1], rb4[3]);
                if (SPLIT) {
                    mma_h(acc[0][2 * jp],     al[0], rb4[0], rb4[2]);
                    mma_h(acc[0][2 * jp + 1], al[0], rb4[1], rb4[3]);
                    mma_h(acc[1][2 * jp],     al[1], rb4[0], rb4[2]);
                    mma_h(acc[1][2 * jp + 1], al[1], rb4[1], rb4[3]);
                }
            }
        }
        __syncthreads();
    }

    // epilogue
#pragma unroll
    for (int j = 0; j < 8; j++) {
        const int col = bn + wn * 64 + j * 8 + 2 * t;
        float2 bv = make_float2(0.f, 0.f);
        if (bias) { bv.x = bias[col]; bv.y = bias[col + 1]; }
#pragma unroll
        for (int i = 0; i < 2; i++) {
            const int row = bm + wm * 32 + i * 16 + g;
            float o0 = acc[i][j][0] + bv.x, o1 = acc[i][j][1] + bv.y;
            float o2 = acc[i][j][2] + bv.x, o3 = acc[i][j][3] + bv.y;
            if (Ch) {
                *(__half2*)(Ch + (size_t)row * N + col) = __floats2half2_rn(o0, o1);
                *(__half2*)(Ch + (size_t)(row + 8) * N + col) = __floats2half2_rn(o2, o3);
            } else {
                *(float2*)(C + (size_t)row * N + col)       = make_float2(o0, o1);
                *(float2*)(C + (size_t)(row + 8) * N + col) = make_float2(o2, o3);
            }
        }
    }
}

// ============================================================
// Fused RMSNorm + RoPE: fp32 in, fp16 out
// ============================================================
__global__ __launch_bounds__(128)
void rmsrope_kernel(const float* __restrict__ q, const float* __restrict__ k,
                    __half* __restrict__ qh, __half* __restrict__ kh,
                    const float* __restrict__ cosb, const float* __restrict__ sinb,
                    const float* __restrict__ qw, const float* __restrict__ kw)
{
    int s  = blockIdx.x;
    int hh = blockIdx.y;
    int d  = threadIdx.x;

    const float* base;
    __half* outp;
    const float* w;
    if (hh < NH) {
        base = q + (size_t)s * HIDN + hh * DH;
        outp = qh + (size_t)s * HIDN + hh * DH;
        w = qw;
    } else {
        base = k + (size_t)s * KVW + (hh - NH) * DH;
        outp = kh + (size_t)s * KVW + (hh - NH) * DH;
        w = kw;
    }

    float val = base[d];
    float ss  = val * val;
#pragma unroll
    for (int off = 16; off >= 1; off >>= 1)
        ss += __shfl_xor_sync(0xffffffffu, ss, off);

    __shared__ float red[4];
    __shared__ float sv[128];
    int lane = d & 31, wid = d >> 5;
    if (lane == 0) red[wid] = ss;
    __syncthreads();
    float tot = red[0] + red[1] + red[2] + red[3];
    float inv = rsqrtf(tot * (1.f / 128.f) + 1e-6f);

    float nv = w[d] * val * inv;
    sv[d] = nv;
    __syncthreads();
    float other = (d < 64) ? -sv[d + 64] : sv[d - 64];
    float res = nv * cosb[(size_t)s * DH + d] + other * sinb[(size_t)s * DH + d];
    outp[d] = __float2half_rn(res);
}

// ============================================================
// Flash attention, fp16 tensor cores, causal. BM=128, BN=64.
// cp.async 3-stage K/V pipeline. 256 threads = 8 warps.
// Output: hi/lo fp16 pair (feeds split O-projection).
// ============================================================
#define QSTR 136
#define A_QB   (128 * QSTR * 2)       // Q bytes
#define A_KB   (64 * QSTR * 2)        // K (or V) tile bytes
#define A_STGB (2 * A_KB)             // K+V stage bytes
#define ATTN_SMEM (A_QB + 3 * A_STGB) // 139264 B

__global__ __launch_bounds__(256)
void attn_h(const __half* __restrict__ Q, const __half* __restrict__ K,
            const __half* __restrict__ V,
            __half* __restrict__ Ohi, __half* __restrict__ Olo)
{
    extern __shared__ __half sh[];
    __half* Qs = sh;
    const uint32_t sbase = (uint32_t)__cvta_generic_to_shared(sh);

    const int tid  = threadIdx.x;
    const int lane = tid & 31, wid = tid >> 5;
    const int g = lane >> 2, t = lane & 3;
    const int h  = blockIdx.y;
    const int tq = (gridDim.x - 1) - blockIdx.x;   // long tiles first
    const int row0 = tq * 128;
    const int kh = h >> 1;                         // GQA reps=2
    const int row_l = wid * 16;

    const int r16 = lane & 15;
    const int q8  = (lane >> 4) << 3;
    const uint32_t qoff = (uint32_t)((row_l + r16) * QSTR + q8) * 2;
    const uint32_t koff = (uint32_t)(r16 * QSTR + q8) * 2;
    const int vm = lane >> 3, vri = lane & 7;
    const uint32_t voff =
        (uint32_t)((vri + ((vm >> 1) << 3)) * QSTR + ((vm & 1) << 3)) * 2;

    const int njt = 2 * tq + 2;

    auto issue = [&](int jt, int s) {
        const int col0 = jt * 64;
        const uint32_t base = sbase + A_QB + (uint32_t)s * A_STGB;
#pragma unroll
        for (int i = 0; i < 4; i++) {
            int idx = tid + (i << 8);
            int row = idx >> 4, c8 = (idx & 15) << 3;
            uint32_t off = (uint32_t)(row * QSTR + c8) * 2;
            cp16(base + off,        K + (size_t)(col0 + row) * KVW + kh * DH + c8);
            cp16(base + A_KB + off, V + (size_t)(col0 + row) * KVW + kh * DH + c8);
        }
        CP_COMMIT();
    };

    // load Q tile (plain LDG)
#pragma unroll
    for (int it = tid; it < 128 * 16; it += 256) {
        int r = it >> 4, c8 = (it & 15) << 3;
        *(uint4*)(Qs + r * QSTR + c8) =
            *(const uint4*)(Q + (size_t)(row0 + r) * HIDN + h * DH + c8);
    }

    issue(0, 0);
    if (njt > 1) issue(1, 1);

    float o[16][4];
#pragma unroll
    for (int jj = 0; jj < 16; jj++)
#pragma unroll
        for (int c = 0; c < 4; c++) o[jj][c] = 0.f;
    float m0 = -INFINITY, m1 = -INFINITY, l0 = 0.f, l1 = 0.f;

    for (int jt = 0; jt < njt; jt++) {
        if (jt < njt - 1) CP_WAIT(1); else CP_WAIT(0);
        __syncthreads();
        if (jt + 2 < njt) issue(jt + 2, (jt + 2) % 3);

        // warps whose rows are entirely above this kv tile: skip compute
        if (jt == 2 * tq + 1 && wid < 4) continue;

        const uint32_t sK = sbase + A_QB + (uint32_t)(jt % 3) * A_STGB;
        const uint32_t sV = sK + A_KB;

        // ---- QK^T ----
        float s[8][4];
#pragma unroll
        for (int j = 0; j < 8; j++)
#pragma unroll
            for (int c = 0; c < 4; c++) s[j][c] = 0.f;

#pragma unroll
        for (int ks = 0; ks < 8; ks++) {
            const uint32_t kb2 = (uint32_t)(ks * 16) * 2;
            uint32_t av[4];
            ldsm_x4(av, sbase + qoff + kb2);
#pragma unroll
            for (int jp = 0; jp < 4; jp++) {
                uint32_t kb4[4];
                ldsm_x4(kb4, sK + koff + kb2 + (uint32_t)(jp * 16 * QSTR) * 2);
                mma_h(s[2 * jp],     av, kb4[0], kb4[2]);
                mma_h(s[2 * jp + 1], av, kb4[1], kb4[3]);
            }
        }

        // ---- softmax (streaming) ----
        const bool diag = (jt >= 2 * tq);
        const int crel = (jt - 2 * tq) * 64;
        const int rg = row_l + g;
        float mx0 = -INFINITY, mx1 = -INFINITY;
#pragma unroll
        for (int j = 0; j < 8; j++) {
            float v0 = s[j][0] * ATT_SCALE, v1 = s[j][1] * ATT_SCALE;
            float v2 = s[j][2] * ATT_SCALE, v3 = s[j][3] * ATT_SCALE;
            if (diag) {
                int c = crel + 8 * j + 2 * t;
                if (c     > rg)     v0 = -1e30f;
                if (c + 1 > rg)     v1 = -1e30f;
                if (c     > rg + 8) v2 = -1e30f;
                if (c + 1 > rg + 8) v3 = -1e30f;
            }
            s[j][0] = v0; s[j][1] = v1; s[j][2] = v2; s[j][3] = v3;
            mx0 = fmaxf(mx0, fmaxf(v0, v1));
            mx1 = fmaxf(mx1, fmaxf(v2, v3));
        }
        mx0 = fmaxf(mx0, __shfl_xor_sync(0xffffffffu, mx0, 1));
        mx0 = fmaxf(mx0, __shfl_xor_sync(0xffffffffu, mx0, 2));
        mx1 = fmaxf(mx1, __shfl_xor_sync(0xffffffffu, mx1, 1));
        mx1 = fmaxf(mx1, __shfl_xor_sync(0xffffffffu, mx1, 2));

        const float mn0 = fmaxf(m0, mx0), mn1 = fmaxf(m1, mx1);
        const float al0 = __expf(m0 - mn0), al1 = __expf(m1 - mn1);
        float ls0 = 0.f, ls1 = 0.f;
#pragma unroll
        for (int j = 0; j < 8; j++) {
            float p0 = __expf(s[j][0] - mn0), p1 = __expf(s[j][1] - mn0);
            float p2 = __expf(s[j][2] - mn1), p3 = __expf(s[j][3] - mn1);
            s[j][0] = p0; s[j][1] = p1; s[j][2] = p2; s[j][3] = p3;
            ls0 += p0 + p1;
            ls1 += p2 + p3;
        }
        ls0 += __shfl_xor_sync(0xffffffffu, ls0, 1);
        ls0 += __shfl_xor_sync(0xffffffffu, ls0, 2);
        ls1 += __shfl_xor_sync(0xffffffffu, ls1, 1);
        ls1 += __shfl_xor_sync(0xffffffffu, ls1, 2);

        l0 = l0 * al0 + ls0;
        l1 = l1 * al1 + ls1;
        m0 = mn0; m1 = mn1;
#pragma unroll
        for (int jj = 0; jj < 16; jj++) {
            o[jj][0] *= al0; o[jj][1] *= al0;
            o[jj][2] *= al1; o[jj][3] *= al1;
        }

        // ---- PV ----
#pragma unroll
        for (int s2 = 0; s2 < 4; s2++) {
            __half2 t0 = __floats2half2_rn(s[2 * s2][0],     s[2 * s2][1]);
            __half2 t1 = __floats2half2_rn(s[2 * s2][2],     s[2 * s2][3]);
            __half2 t2 = __floats2half2_rn(s[2 * s2 + 1][0], s[2 * s2 + 1][1]);
            __half2 t3 = __floats2half2_rn(s[2 * s2 + 1][2], s[2 * s2 + 1][3]);
            uint32_t pa[4];
            pa[0] = *(uint32_t*)&t0;
            pa[1] = *(uint32_t*)&t1;
            pa[2] = *(uint32_t*)&t2;
            pa[3] = *(uint32_t*)&t3;
            const uint32_t vrow2 = (uint32_t)(s2 * 16 * QSTR) * 2;
#pragma unroll
            for (int djp = 0; djp < 8; djp++) {
                uint32_t vb[4];
                ldsm_x4_t(vb, sV + voff + vrow2 + (uint32_t)(djp * 16) * 2);
                mma_h(o[2 * djp],     pa, vb[0], vb[2]);
                mma_h(o[2 * djp + 1], pa, vb[1], vb[3]);
            }
        }
    }

    // epilogue: write hi/lo fp16 pair
    const float i0 = 1.f / l0, i1 = 1.f / l1;
    const int gr0 = row0 + row_l + g, gr1 = gr0 + 8;
#pragma unroll
    for (int jj = 0; jj < 16; jj++) {
        const int col = h * DH + jj * 8 + 2 * t;
        float v00 = o[jj][0] * i0, v01 = o[jj][1] * i0;
        float v10 = o[jj][2] * i1, v11 = o[jj][3] * i1;
        __half h00 = __float2half_rn(v00), h01 = __float2half_rn(v01);
        __half h10 = __float2half_rn(v10), h11 = __float2half_rn(v11);
        *(__half2*)(Ohi + (size_t)gr0 * HIDN + col) = __halves2half2(h00, h01);
        *(__half2*)(Ohi + (size_t)gr1 * HIDN + col) = __halves2half2(h10, h11);
        *(__half2*)(Olo + (size_t)gr0 * HIDN + col) = __halves2half2(
            __float2half_rn(v00 - __half2float(h00)),
            __float2half_rn(v01 - __half2float(h01)));
        *(__half2*)(Olo + (size_t)gr1 * HIDN + col) = __halves2half2(
            __float2half_rn(v10 - __half2float(h10)),
            __float2half_rn(v11 - __half2float(h11)));
    }
}

// ============================================================
// launch
// ============================================================
extern "C" void kernel_launch(void* const* d_in, const int* in_sizes, int n_in,
                              void* d_out, int out_size)
{
    const float* x    = (const float*)d_in[0];
    const float* cosb = (const float*)d_in[1];
    const float* sinb = (const float*)d_in[2];
    // d_in[3] = mask: ignored (exactly causal, implemented analytically)
    const float* Wq = (const float*)d_in[4];
    const float* bq = (const float*)d_in[5];
    const float* Wk = (const float*)d_in[6];
    const float* bk = (const float*)d_in[7];
    const float* Wv = (const float*)d_in[8];
    const float* bv = (const float*)d_in[9];
    const float* Wo = (const float*)d_in[10];
    const float* qw = (const float*)d_in[11];
    const float* kw = (const float*)d_in[12];
    float* out = (float*)d_out;

    float *qp, *kp;
    __half *xh, *wq, *wk, *wv, *wo, *qhp, *khp, *vhp, *ohi, *olo;
    cudaGetSymbolAddress((void**)&qp,  g_q);
    cudaGetSymbolAddress((void**)&kp,  g_k);
    cudaGetSymbolAddress((void**)&xh,  g_xh);
    cudaGetSymbolAddress((void**)&wq,  g_wq);
    cudaGetSymbolAddress((void**)&wk,  g_wk);
    cudaGetSymbolAddress((void**)&wv,  g_wv);
    cudaGetSymbolAddress((void**)&wo,  g_wo);
    cudaGetSymbolAddress((void**)&qhp, g_qh);
    cudaGetSymbolAddress((void**)&khp, g_kh);
    cudaGetSymbolAddress((void**)&vhp, g_vh);
    cudaGetSymbolAddress((void**)&ohi, g_ohi);
    cudaGetSymbolAddress((void**)&olo, g_olo);

    cudaFuncSetAttribute(attn_h, cudaFuncAttributeMaxDynamicSharedMemorySize,
                         ATTN_SMEM);
    cudaFuncSetAttribute(gemm_a<false>,
                         cudaFuncAttributeMaxDynamicSharedMemorySize, 3 * 2 * G_ASB);
    cudaFuncSetAttribute(gemm_a<true>,
                         cudaFuncAttributeMaxDynamicSharedMemorySize, 3 * 3 * G_ASB);

    // fp32 -> fp16 conversions
    auto f2h = [&](const float* s, __half* d, size_t n) {
        int n4 = (int)(n >> 2);
        f2h_kernel<<<(n4 + 255) / 256, 256>>>((const float4*)s, (__half2*)d, n4);
    };
    f2h(x,  xh, (size_t)S_LEN * HIDN);
    f2h(Wq, wq, (size_t)HIDN * HIDN);
    f2h(Wk, wk, (size_t)KVW * HIDN);
    f2h(Wv, wv, (size_t)KVW * HIDN);
    f2h(Wo, wo, (size_t)HIDN * HIDN);

    dim3 blk(256);
    const int gsm2 = 3 * 2 * G_ASB, gsm3 = 3 * 3 * G_ASB;
    gemm_a<false><<<dim3(16, 32), blk, gsm2>>>(xh, nullptr, wq, bq, qp, nullptr,
                                               S_LEN, HIDN, HIDN);
    gemm_a<false><<<dim3(8, 32),  blk, gsm2>>>(xh, nullptr, wk, bk, kp, nullptr,
                                               S_LEN, KVW, HIDN);
    gemm_a<false><<<dim3(8, 32),  blk, gsm2>>>(xh, nullptr, wv, bv, nullptr, vhp,
                                               S_LEN, KVW, HIDN);

    rmsrope_kernel<<<dim3(S_LEN, NH + NKV), 128>>>(qp, kp, qhp, khp,
                                                   cosb, sinb, qw, kw);

    attn_h<<<dim3(32, NH), 256, ATTN_SMEM>>>(qhp, khp, vhp, ohi, olo);

    gemm_a<true><<<dim3(16, 32), blk, gsm3>>>(ohi, olo, wo, nullptr, out, nullptr,
                                              S_LEN, HIDN, HIDN);
}

// round 9
// speedup vs baseline: 7.7097x; 1.1816x over previous
#include <cuda_runtime.h>
#include <cuda_fp16.h>
#include <math.h>
#include <cstdint>

#define S_LEN 4096
#define HIDN  2048
#define NH    16
#define NKV   8
#define DH    128
#define KVW   (NKV*DH)      // 1024
#define ATT_SCALE 0.08838834764831845f   // 1/sqrt(128)

// -------- scratch (device globals: allocation-free) --------
__device__ float  g_q  [(size_t)S_LEN * HIDN];   // fp32 q (pre-norm)
__device__ float  g_k  [(size_t)S_LEN * KVW];    // fp32 k (pre-norm)
__device__ __half g_xh [(size_t)S_LEN * HIDN];   // fp16 x
__device__ __half g_wq [(size_t)HIDN * HIDN];
__device__ __half g_wk [(size_t)KVW  * HIDN];
__device__ __half g_wv [(size_t)KVW  * HIDN];
__device__ __half g_wo [(size_t)HIDN * HIDN];
__device__ __half g_qh [(size_t)S_LEN * HIDN];
__device__ __half g_kh [(size_t)S_LEN * KVW];
__device__ __half g_vh [(size_t)S_LEN * KVW];
__device__ __half g_oh [(size_t)S_LEN * HIDN];   // attn out fp16

// ---------------- PTX helpers ----------------
__device__ __forceinline__ void mma_h(float* d, const uint32_t* a,
                                      uint32_t b0, uint32_t b1) {
    asm volatile(
        "mma.sync.aligned.m16n8k16.row.col.f32.f16.f16.f32 "
        "{%0,%1,%2,%3}, {%4,%5,%6,%7}, {%8,%9}, {%0,%1,%2,%3};"
        : "+f"(d[0]), "+f"(d[1]), "+f"(d[2]), "+f"(d[3])
        : "r"(a[0]), "r"(a[1]), "r"(a[2]), "r"(a[3]), "r"(b0), "r"(b1));
}
__device__ __forceinline__ void ldsm_x4(uint32_t* r, uint32_t addr) {
    asm volatile("ldmatrix.sync.aligned.m8n8.x4.shared.b16 {%0,%1,%2,%3}, [%4];"
        : "=r"(r[0]), "=r"(r[1]), "=r"(r[2]), "=r"(r[3]) : "r"(addr));
}
__device__ __forceinline__ void ldsm_x4_t(uint32_t* r, uint32_t addr) {
    asm volatile("ldmatrix.sync.aligned.m8n8.x4.trans.shared.b16 {%0,%1,%2,%3}, [%4];"
        : "=r"(r[0]), "=r"(r[1]), "=r"(r[2]), "=r"(r[3]) : "r"(addr));
}
__device__ __forceinline__ void cp16(uint32_t dst, const void* src) {
    asm volatile("cp.async.cg.shared.global [%0], [%1], 16;" :: "r"(dst), "l"(src));
}
#define CP_COMMIT() asm volatile("cp.async.commit_group;" ::: "memory")
#define CP_WAIT(n)  asm volatile("cp.async.wait_group %0;" :: "n"(n) : "memory")

// ============================================================
// fused fp32 -> fp16 conversion for x, Wq, Wk, Wv, Wo
// ============================================================
#define N4_X  ((S_LEN * HIDN) / 4)
#define N4_WQ ((HIDN * HIDN) / 4)
#define N4_WK ((KVW * HIDN) / 4)
#define N4_TOT (N4_X + N4_WQ + 2 * N4_WK + N4_WQ)

__global__ __launch_bounds__(256)
void f2h_all(const float4* __restrict__ x,  const float4* __restrict__ wq,
             const float4* __restrict__ wk, const float4* __restrict__ wv,
             const float4* __restrict__ wo)
{
    int i = blockIdx.x * blockDim.x + threadIdx.x;
    if (i >= N4_TOT) return;
    const float4* src;
    __half2* dst;
    int off;
    if (i < N4_X) {
        src = x;  dst = (__half2*)g_xh; off = i;
    } else if (i < N4_X + N4_WQ) {
        src = wq; dst = (__half2*)g_wq; off = i - N4_X;
    } else if (i < N4_X + N4_WQ + N4_WK) {
        src = wk; dst = (__half2*)g_wk; off = i - N4_X - N4_WQ;
    } else if (i < N4_X + N4_WQ + 2 * N4_WK) {
        src = wv; dst = (__half2*)g_wv; off = i - N4_X - N4_WQ - N4_WK;
    } else {
        src = wo; dst = (__half2*)g_wo; off = i - N4_X - N4_WQ - 2 * N4_WK;
    }
    float4 v = src[off];
    dst[2 * off]     = __floats2half2_rn(v.x, v.y);
    dst[2 * off + 1] = __floats2half2_rn(v.z, v.w);
}

// ============================================================
// GEMM (all-fp16 operands, cp.async 3-stage pipeline):
// C[m][n] = sum_k A[m][k]*B[n][k] + bias[n]
// BM=BN=128, BK=32, 256 threads (8 warps 4x2), warp tile 32x64.
// ============================================================
#define APAD 40
#define G_AS   (128 * APAD)
#define G_ASB  (G_AS * 2)
#define G_STGB (2 * G_ASB)
#define G_SMEM (3 * G_STGB)   // 61440 B

__global__ __launch_bounds__(256)
void gemm_a(const __half* __restrict__ Ah, const __half* __restrict__ Bh,
            const float* __restrict__ bias,
            float* __restrict__ C, __half* __restrict__ Ch,
            int M, int N, int K)
{
    extern __shared__ __half sm[];
    const uint32_t sbase = (uint32_t)__cvta_generic_to_shared(sm);

    const int tid  = threadIdx.x;
    const int lane = tid & 31, wid = tid >> 5;
    const int g = lane >> 2, t = lane & 3;
    const int wm = wid & 3, wn = wid >> 2;
    const int bm = blockIdx.y * 128, bn = blockIdx.x * 128;
    const int r16 = lane & 15;
    const int q8  = (lane >> 4) << 3;

    float acc[2][8][4];
#pragma unroll
    for (int i = 0; i < 2; i++)
#pragma unroll
        for (int j = 0; j < 8; j++)
#pragma unroll
            for (int c = 0; c < 4; c++) acc[i][j][c] = 0.f;

    auto issue = [&](int k0, int s) {
        const uint32_t sa = sbase + (uint32_t)s * G_STGB;
#pragma unroll
        for (int i = 0; i < 2; i++) {
            int idx = tid + (i << 8);
            int row = idx >> 2, c8 = (idx & 3) << 3;
            uint32_t off = (uint32_t)(row * APAD + c8) * 2;
            cp16(sa + off,         Ah + (size_t)(bm + row) * K + k0 + c8);
            cp16(sa + G_ASB + off, Bh + (size_t)(bn + row) * K + k0 + c8);
        }
        CP_COMMIT();
    };

    const int nk = K >> 5;
    issue(0, 0);
    issue(32, 1);

    const int ab = wm * 32, bb = wn * 64;
    const uint32_t aoff = (uint32_t)((ab + r16) * APAD + q8) * 2;
    const uint32_t boff = (uint32_t)((bb + r16) * APAD + q8) * 2;

    for (int it = 0; it < nk; ++it) {
        if (it < nk - 1) CP_WAIT(1); else CP_WAIT(0);
        __syncthreads();
        if (it + 2 < nk) issue((it + 2) << 5, (it + 2) % 3);

        const uint32_t sA = sbase + (uint32_t)(it % 3) * G_STGB;
        const uint32_t sB = sA + G_ASB;

#pragma unroll
        for (int ks = 0; ks < 2; ks++) {
            const uint32_t kb2 = (uint32_t)(ks * 16) * 2;
            uint32_t ah[2][4];
#pragma unroll
            for (int i = 0; i < 2; i++)
                ldsm_x4(ah[i], sA + aoff + kb2 + (uint32_t)(i * 16 * APAD) * 2);
#pragma unroll
            for (int jp = 0; jp < 4; jp++) {
                uint32_t rb4[4];
                ldsm_x4(rb4, sB + boff + kb2 + (uint32_t)(jp * 16 * APAD) * 2);
                mma_h(acc[0][2 * jp],     ah[0], rb4[0], rb4[2]);
                mma_h(acc[0][2 * jp + 1], ah[0], rb4[1], rb4[3]);
                mma_h(acc[1][2 * jp],     ah[1], rb4[0], rb4[2]);
                mma_h(acc[1][2 * jp + 1], ah[1], rb4[1], rb4[3]);
            }
        }
        __syncthreads();
    }

    // epilogue
#pragma unroll
    for (int j = 0; j < 8; j++) {
        const int col = bn + wn * 64 + j * 8 + 2 * t;
        float2 bv = make_float2(0.f, 0.f);
        if (bias) { bv.x = bias[col]; bv.y = bias[col + 1]; }
#pragma unroll
        for (int i = 0; i < 2; i++) {
            const int row = bm + wm * 32 + i * 16 + g;
            float o0 = acc[i][j][0] + bv.x, o1 = acc[i][j][1] + bv.y;
            float o2 = acc[i][j][2] + bv.x, o3 = acc[i][j][3] + bv.y;
            if (Ch) {
                *(__half2*)(Ch + (size_t)row * N + col) = __floats2half2_rn(o0, o1);
                *(__half2*)(Ch + (size_t)(row + 8) * N + col) = __floats2half2_rn(o2, o3);
            } else {
                *(float2*)(C + (size_t)row * N + col)       = make_float2(o0, o1);
                *(float2*)(C + (size_t)(row + 8) * N + col) = make_float2(o2, o3);
            }
        }
    }
}

// ============================================================
// Fused RMSNorm + RoPE: one warp per (token, head) row.
// float4 loads, warp-shuffle reduction + rotate-half. fp16 out.
// grid (512, 24), block 256 (8 warps = 8 tokens per block).
// ============================================================
__global__ __launch_bounds__(256)
void rmsrope_kernel(const float* __restrict__ q, const float* __restrict__ k,
                    __half* __restrict__ qh, __half* __restrict__ kh,
                    const float* __restrict__ cosb, const float* __restrict__ sinb,
                    const float* __restrict__ qw, const float* __restrict__ kw)
{
    const int wid  = threadIdx.x >> 5, lane = threadIdx.x & 31;
    const int s    = blockIdx.x * 8 + wid;
    const int hh   = blockIdx.y;

    const float* base;
    __half* outp;
    const float* w;
    if (hh < NH) {
        base = q + (size_t)s * HIDN + hh * DH;
        outp = qh + (size_t)s * HIDN + hh * DH;
        w = qw;
    } else {
        base = k + (size_t)s * KVW + (hh - NH) * DH;
        outp = kh + (size_t)s * KVW + (hh - NH) * DH;
        w = kw;
    }

    float4 v = *(const float4*)(base + 4 * lane);
    float ss = v.x * v.x + v.y * v.y + v.z * v.z + v.w * v.w;
#pragma unroll
    for (int off = 16; off >= 1; off >>= 1)
        ss += __shfl_xor_sync(0xffffffffu, ss, off);
    const float inv = rsqrtf(ss * (1.f / 128.f) + 1e-6f);

    float4 wv = *(const float4*)(w + 4 * lane);
    float4 nv;
    nv.x = wv.x * v.x * inv; nv.y = wv.y * v.y * inv;
    nv.z = wv.z * v.z * inv; nv.w = wv.w * v.w * inv;

    // rotate_half: partner element d +/- 64 lives in lane^16, same slot
    float4 ov;
    ov.x = __shfl_xor_sync(0xffffffffu, nv.x, 16);
    ov.y = __shfl_xor_sync(0xffffffffu, nv.y, 16);
    ov.z = __shfl_xor_sync(0xffffffffu, nv.z, 16);
    ov.w = __shfl_xor_sync(0xffffffffu, nv.w, 16);
    const float sgn = (lane < 16) ? -1.f : 1.f;

    const float4 cv = *(const float4*)(cosb + (size_t)s * DH + 4 * lane);
    const float4 sv = *(const float4*)(sinb + (size_t)s * DH + 4 * lane);
    float r0 = nv.x * cv.x + sgn * ov.x * sv.x;
    float r1 = nv.y * cv.y + sgn * ov.y * sv.y;
    float r2 = nv.z * cv.z + sgn * ov.z * sv.z;
    float r3 = nv.w * cv.w + sgn * ov.w * sv.w;

    __half2 h01 = __floats2half2_rn(r0, r1);
    __half2 h23 = __floats2half2_rn(r2, r3);
    uint2 pack;
    pack.x = *(uint32_t*)&h01;
    pack.y = *(uint32_t*)&h23;
    *(uint2*)(outp + 4 * lane) = pack;
}

// ============================================================
// Flash attention, fp16 tensor cores, causal. BM=128, BN=64.
// cp.async 3-stage K/V pipeline. 256 threads = 8 warps.
// ============================================================
#define QSTR 136
#define A_QB   (128 * QSTR * 2)
#define A_KB   (64 * QSTR * 2)
#define A_STGB (2 * A_KB)
#define ATTN_SMEM (A_QB + 3 * A_STGB) // 139264 B

__global__ __launch_bounds__(256)
void attn_h(const __half* __restrict__ Q, const __half* __restrict__ K,
            const __half* __restrict__ V, __half* __restrict__ Oh)
{
    extern __shared__ __half sh[];
    __half* Qs = sh;
    const uint32_t sbase = (uint32_t)__cvta_generic_to_shared(sh);

    const int tid  = threadIdx.x;
    const int lane = tid & 31, wid = tid >> 5;
    const int g = lane >> 2, t = lane & 3;
    const int h  = blockIdx.y;
    const int tq = (gridDim.x - 1) - blockIdx.x;
    const int row0 = tq * 128;
    const int kh = h >> 1;
    const int row_l = wid * 16;

    const int r16 = lane & 15;
    const int q8  = (lane >> 4) << 3;
    const uint32_t qoff = (uint32_t)((row_l + r16) * QSTR + q8) * 2;
    const uint32_t koff = (uint32_t)(r16 * QSTR + q8) * 2;
    const int vm = lane >> 3, vri = lane & 7;
    const uint32_t voff =
        (uint32_t)((vri + ((vm >> 1) << 3)) * QSTR + ((vm & 1) << 3)) * 2;

    const int njt = 2 * tq + 2;

    auto issue = [&](int jt, int s) {
        const int col0 = jt * 64;
        const uint32_t base = sbase + A_QB + (uint32_t)s * A_STGB;
#pragma unroll
        for (int i = 0; i < 4; i++) {
            int idx = tid + (i << 8);
            int row = idx >> 4, c8 = (idx & 15) << 3;
            uint32_t off = (uint32_t)(row * QSTR + c8) * 2;
            cp16(base + off,        K + (size_t)(col0 + row) * KVW + kh * DH + c8);
            cp16(base + A_KB + off, V + (size_t)(col0 + row) * KVW + kh * DH + c8);
        }
        CP_COMMIT();
    };

#pragma unroll
    for (int it = tid; it < 128 * 16; it += 256) {
        int r = it >> 4, c8 = (it & 15) << 3;
        *(uint4*)(Qs + r * QSTR + c8) =
            *(const uint4*)(Q + (size_t)(row0 + r) * HIDN + h * DH + c8);
    }

    issue(0, 0);
    if (njt > 1) issue(1, 1);

    float o[16][4];
#pragma unroll
    for (int jj = 0; jj < 16; jj++)
#pragma unroll
        for (int c = 0; c < 4; c++) o[jj][c] = 0.f;
    float m0 = -INFINITY, m1 = -INFINITY, l0 = 0.f, l1 = 0.f;

    for (int jt = 0; jt < njt; jt++) {
        if (jt < njt - 1) CP_WAIT(1); else CP_WAIT(0);
        __syncthreads();
        if (jt + 2 < njt) issue(jt + 2, (jt + 2) % 3);

        if (jt == 2 * tq + 1 && wid < 4) continue;

        const uint32_t sK = sbase + A_QB + (uint32_t)(jt % 3) * A_STGB;
        const uint32_t sV = sK + A_KB;

        // ---- QK^T ----
        float s[8][4];
#pragma unroll
        for (int j = 0; j < 8; j++)
#pragma unroll
            for (int c = 0; c < 4; c++) s[j][c] = 0.f;

#pragma unroll
        for (int ks = 0; ks < 8; ks++) {
            const uint32_t kb2 = (uint32_t)(ks * 16) * 2;
            uint32_t av[4];
            ldsm_x4(av, sbase + qoff + kb2);
#pragma unroll
            for (int jp = 0; jp < 4; jp++) {
                uint32_t kb4[4];
                ldsm_x4(kb4, sK + koff + kb2 + (uint32_t)(jp * 16 * QSTR) * 2);
                mma_h(s[2 * jp],     av, kb4[0], kb4[2]);
                mma_h(s[2 * jp + 1], av, kb4[1], kb4[3]);
            }
        }

        // ---- softmax ----
        const bool diag = (jt >= 2 * tq);
        const int crel = (jt - 2 * tq) * 64;
        const int rg = row_l + g;
        float mx0 = -INFINITY, mx1 = -INFINITY;
#pragma unroll
        for (int j = 0; j < 8; j++) {
            float v0 = s[j][0] * ATT_SCALE, v1 = s[j][1] * ATT_SCALE;
            float v2 = s[j][2] * ATT_SCALE, v3 = s[j][3] * ATT_SCALE;
            if (diag) {
                int c = crel + 8 * j + 2 * t;
                if (c     > rg)     v0 = -1e30f;
                if (c + 1 > rg)     v1 = -1e30f;
                if (c     > rg + 8) v2 = -1e30f;
                if (c + 1 > rg + 8) v3 = -1e30f;
            }
            s[j][0] = v0; s[j][1] = v1; s[j][2] = v2; s[j][3] = v3;
            mx0 = fmaxf(mx0, fmaxf(v0, v1));
            mx1 = fmaxf(mx1, fmaxf(v2, v3));
        }
        mx0 = fmaxf(mx0, __shfl_xor_sync(0xffffffffu, mx0, 1));
        mx0 = fmaxf(mx0, __shfl_xor_sync(0xffffffffu, mx0, 2));
        mx1 = fmaxf(mx1, __shfl_xor_sync(0xffffffffu, mx1, 1));
        mx1 = fmaxf(mx1, __shfl_xor_sync(0xffffffffu, mx1, 2));

        const float mn0 = fmaxf(m0, mx0), mn1 = fmaxf(m1, mx1);
        const float al0 = __expf(m0 - mn0), al1 = __expf(m1 - mn1);
        float ls0 = 0.f, ls1 = 0.f;
#pragma unroll
        for (int j = 0; j < 8; j++) {
            float p0 = __expf(s[j][0] - mn0), p1 = __expf(s[j][1] - mn0);
            float p2 = __expf(s[j][2] - mn1), p3 = __expf(s[j][3] - mn1);
            s[j][0] = p0; s[j][1] = p1; s[j][2] = p2; s[j][3] = p3;
            ls0 += p0 + p1;
            ls1 += p2 + p3;
        }
        ls0 += __shfl_xor_sync(0xffffffffu, ls0, 1);
        ls0 += __shfl_xor_sync(0xffffffffu, ls0, 2);
        ls1 += __shfl_xor_sync(0xffffffffu, ls1, 1);
        ls1 += __shfl_xor_sync(0xffffffffu, ls1, 2);

        l0 = l0 * al0 + ls0;
        l1 = l1 * al1 + ls1;
        m0 = mn0; m1 = mn1;
#pragma unroll
        for (int jj = 0; jj < 16; jj++) {
            o[jj][0] *= al0; o[jj][1] *= al0;
            o[jj][2] *= al1; o[jj][3] *= al1;
        }

        // ---- PV ----
#pragma unroll
        for (int s2 = 0; s2 < 4; s2++) {
            __half2 t0 = __floats2half2_rn(s[2 * s2][0],     s[2 * s2][1]);
            __half2 t1 = __floats2half2_rn(s[2 * s2][2],     s[2 * s2][3]);
            __half2 t2 = __floats2half2_rn(s[2 * s2 + 1][0], s[2 * s2 + 1][1]);
            __half2 t3 = __floats2half2_rn(s[2 * s2 + 1][2], s[2 * s2 + 1][3]);
            uint32_t pa[4];
            pa[0] = *(uint32_t*)&t0;
            pa[1] = *(uint32_t*)&t1;
            pa[2] = *(uint32_t*)&t2;
            pa[3] = *(uint32_t*)&t3;
            const uint32_t vrow2 = (uint32_t)(s2 * 16 * QSTR) * 2;
#pragma unroll
            for (int djp = 0; djp < 8; djp++) {
                uint32_t vb[4];
                ldsm_x4_t(vb, sV + voff + vrow2 + (uint32_t)(djp * 16) * 2);
                mma_h(o[2 * djp],     pa, vb[0], vb[2]);
                mma_h(o[2 * djp + 1], pa, vb[1], vb[3]);
            }
        }
    }

    // epilogue: fp16 out
    const float i0 = 1.f / l0, i1 = 1.f / l1;
    const int gr0 = row0 + row_l + g, gr1 = gr0 + 8;
#pragma unroll
    for (int jj = 0; jj < 16; jj++) {
        const int col = h * DH + jj * 8 + 2 * t;
        *(__half2*)(Oh + (size_t)gr0 * HIDN + col) =
            __floats2half2_rn(o[jj][0] * i0, o[jj][1] * i0);
        *(__half2*)(Oh + (size_t)gr1 * HIDN + col) =
            __floats2half2_rn(o[jj][2] * i1, o[jj][3] * i1);
    }
}

// ============================================================
// launch
// ============================================================
extern "C" void kernel_launch(void* const* d_in, const int* in_sizes, int n_in,
                              void* d_out, int out_size)
{
    const float* x    = (const float*)d_in[0];
    const float* cosb = (const float*)d_in[1];
    const float* sinb = (const float*)d_in[2];
    // d_in[3] = mask: ignored (exactly causal, implemented analytically)
    const float* Wq = (const float*)d_in[4];
    const float* bq = (const float*)d_in[5];
    const float* Wk = (const float*)d_in[6];
    const float* bk = (const float*)d_in[7];
    const float* Wv = (const float*)d_in[8];
    const float* bv = (const float*)d_in[9];
    const float* Wo = (const float*)d_in[10];
    const float* qw = (const float*)d_in[11];
    const float* kw = (const float*)d_in[12];
    float* out = (float*)d_out;

    float *qp, *kp;
    __half *xh, *wq, *wk, *wv, *wo, *qhp, *khp, *vhp, *oh;
    cudaGetSymbolAddress((void**)&qp,  g_q);
    cudaGetSymbolAddress((void**)&kp,  g_k);
    cudaGetSymbolAddress((void**)&xh,  g_xh);
    cudaGetSymbolAddress((void**)&wq,  g_wq);
    cudaGetSymbolAddress((void**)&wk,  g_wk);
    cudaGetSymbolAddress((void**)&wv,  g_wv);
    cudaGetSymbolAddress((void**)&wo,  g_wo);
    cudaGetSymbolAddress((void**)&qhp, g_qh);
    cudaGetSymbolAddress((void**)&khp, g_kh);
    cudaGetSymbolAddress((void**)&vhp, g_vh);
    cudaGetSymbolAddress((void**)&oh,  g_oh);

    cudaFuncSetAttribute(attn_h, cudaFuncAttributeMaxDynamicSharedMemorySize,
                         ATTN_SMEM);
    cudaFuncSetAttribute(gemm_a, cudaFuncAttributeMaxDynamicSharedMemorySize,
                         G_SMEM);

    f2h_all<<<(N4_TOT + 255) / 256, 256>>>((const float4*)x, (const float4*)Wq,
                                           (const float4*)Wk, (const float4*)Wv,
                                           (const float4*)Wo);

    dim3 blk(256);
    gemm_a<<<dim3(16, 32), blk, G_SMEM>>>(xh, wq, bq, qp, nullptr,
                                          S_LEN, HIDN, HIDN);
    gemm_a<<<dim3(8, 32),  blk, G_SMEM>>>(xh, wk, bk, kp, nullptr,
                                          S_LEN, KVW, HIDN);
    gemm_a<<<dim3(8, 32),  blk, G_SMEM>>>(xh, wv, bv, nullptr, vhp,
                                          S_LEN, KVW, HIDN);

    rmsrope_kernel<<<dim3(S_LEN / 8, NH + NKV), 256>>>(qp, kp, qhp, khp,
                                                       cosb, sinb, qw, kw);

    attn_h<<<dim3(32, NH), 256, ATTN_SMEM>>>(qhp, khp, vhp, oh);

    gemm_a<<<dim3(16, 32), blk, G_SMEM>>>(oh, wo, nullptr, out, nullptr,
                                          S_LEN, HIDN, HIDN);
}

// round 10
// speedup vs baseline: 8.3454x; 1.0825x over previous
#include <cuda_runtime.h>
#include <cuda_fp16.h>
#include <math.h>
#include <cstdint>

#define S_LEN 4096
#define HIDN  2048
#define NH    16
#define NKV   8
#define DH    128
#define KVW   (NKV*DH)      // 1024
#define NQKV  (HIDN + 2*KVW)  // 4096
#define ATT_SCALE 0.08838834764831845f

// -------- scratch (device globals: allocation-free) --------
__device__ float  g_q  [(size_t)S_LEN * HIDN];
__device__ float  g_k  [(size_t)S_LEN * KVW];
__device__ __half g_xh [(size_t)S_LEN * HIDN];
__device__ __half g_wq [(size_t)HIDN * HIDN];
__device__ __half g_wk [(size_t)KVW  * HIDN];
__device__ __half g_wv [(size_t)KVW  * HIDN];
__device__ __half g_wo [(size_t)HIDN * HIDN];
__device__ float  g_bias[NQKV];                 // concat bq|bk|bv
__device__ __half g_qh [(size_t)S_LEN * HIDN];
__device__ __half g_kh [(size_t)S_LEN * KVW];
__device__ __half g_vh [(size_t)S_LEN * KVW];
__device__ __half g_oh [(size_t)S_LEN * HIDN];

// ---------------- PTX helpers ----------------
__device__ __forceinline__ void mma_h(float* d, const uint32_t* a,
                                      uint32_t b0, uint32_t b1) {
    asm volatile(
        "mma.sync.aligned.m16n8k16.row.col.f32.f16.f16.f32 "
        "{%0,%1,%2,%3}, {%4,%5,%6,%7}, {%8,%9}, {%0,%1,%2,%3};"
        : "+f"(d[0]), "+f"(d[1]), "+f"(d[2]), "+f"(d[3])
        : "r"(a[0]), "r"(a[1]), "r"(a[2]), "r"(a[3]), "r"(b0), "r"(b1));
}
__device__ __forceinline__ void ldsm_x4(uint32_t* r, uint32_t addr) {
    asm volatile("ldmatrix.sync.aligned.m8n8.x4.shared.b16 {%0,%1,%2,%3}, [%4];"
        : "=r"(r[0]), "=r"(r[1]), "=r"(r[2]), "=r"(r[3]) : "r"(addr));
}
__device__ __forceinline__ void ldsm_x4_t(uint32_t* r, uint32_t addr) {
    asm volatile("ldmatrix.sync.aligned.m8n8.x4.trans.shared.b16 {%0,%1,%2,%3}, [%4];"
        : "=r"(r[0]), "=r"(r[1]), "=r"(r[2]), "=r"(r[3]) : "r"(addr));
}
__device__ __forceinline__ void cp16(uint32_t dst, const void* src) {
    asm volatile("cp.async.cg.shared.global [%0], [%1], 16;" :: "r"(dst), "l"(src));
}
#define CP_COMMIT() asm volatile("cp.async.commit_group;" ::: "memory")
#define CP_WAIT(n)  asm volatile("cp.async.wait_group %0;" :: "n"(n) : "memory")

// ============================================================
// fused fp32 -> fp16 conversion + bias concat
// ============================================================
#define N4_X  ((S_LEN * HIDN) / 4)
#define N4_WQ ((HIDN * HIDN) / 4)
#define N4_WK ((KVW * HIDN) / 4)
#define N4_W_END (N4_X + 2 * N4_WQ + 2 * N4_WK)
#define N4_TOT   (N4_W_END + NQKV / 4)

__global__ __launch_bounds__(256)
void f2h_all(const float4* __restrict__ x,  const float4* __restrict__ wq,
             const float4* __restrict__ wk, const float4* __restrict__ wv,
             const float4* __restrict__ wo,
             const float* __restrict__ bq, const float* __restrict__ bk,
             const float* __restrict__ bv)
{
    int i = blockIdx.x * blockDim.x + threadIdx.x;
    if (i >= N4_TOT) return;
    if (i >= N4_W_END) {                       // bias concat (fp32 copy)
        int col = (i - N4_W_END) * 4;
        const float* src = (col < HIDN) ? bq + col
                         : (col < HIDN + KVW) ? bk + (col - HIDN)
                         : bv + (col - HIDN - KVW);
        *(float4*)(g_bias + col) = *(const float4*)src;
        return;
    }
    const float4* src;
    __half2* dst;
    int off;
    if (i < N4_X) {
        src = x;  dst = (__half2*)g_xh; off = i;
    } else if (i < N4_X + N4_WQ) {
        src = wq; dst = (__half2*)g_wq; off = i - N4_X;
    } else if (i < N4_X + N4_WQ + N4_WK) {
        src = wk; dst = (__half2*)g_wk; off = i - N4_X - N4_WQ;
    } else if (i < N4_X + N4_WQ + 2 * N4_WK) {
        src = wv; dst = (__half2*)g_wv; off = i - N4_X - N4_WQ - N4_WK;
    } else {
        src = wo; dst = (__half2*)g_wo; off = i - N4_X - N4_WQ - 2 * N4_WK;
    }
    float4 v = src[off];
    dst[2 * off]     = __floats2half2_rn(v.x, v.y);
    dst[2 * off + 1] = __floats2half2_rn(v.z, v.w);
}

// ============================================================
// GEMM (fp16, cp.async 4-stage). MODE 0: C fp32 (+bias param)
// MODE 2: fused QKV (B/bias/dest from globals, N=4096 routed)
// BM=BN=128, BK=32, 256 threads (8 warps 4x2).
// ============================================================
#define APAD 40
#define G_ASB  (128 * APAD * 2)
#define G_STGB (2 * G_ASB)
#define G_SMEM (4 * G_STGB)   // 81920 B

template<int MODE>
__global__ __launch_bounds__(256, 2)
void gemm_a(const __half* __restrict__ Ah, const __half* __restrict__ Bh,
            const float* __restrict__ bias, float* __restrict__ C,
            int M, int N, int K)
{
    extern __shared__ __half sm[];
    const uint32_t sbase = (uint32_t)__cvta_generic_to_shared(sm);

    const int tid  = threadIdx.x;
    const int lane = tid & 31, wid = tid >> 5;
    const int g = lane >> 2, t = lane & 3;
    const int wm = wid & 3, wn = wid >> 2;
    const int bm = blockIdx.y * 128, bn = blockIdx.x * 128;
    const int r16 = lane & 15;
    const int q8  = (lane >> 4) << 3;

    // B source select (MODE 2 routes across wq|wk|wv)
    const __half* Bsel;
    int bnl;
    if (MODE == 2) {
        if (bn < HIDN)            { Bsel = g_wq; bnl = bn; }
        else if (bn < HIDN + KVW) { Bsel = g_wk; bnl = bn - HIDN; }
        else                      { Bsel = g_wv; bnl = bn - HIDN - KVW; }
    } else {
        Bsel = Bh; bnl = bn;
    }

    float acc[2][8][4];
#pragma unroll
    for (int i = 0; i < 2; i++)
#pragma unroll
        for (int j = 0; j < 8; j++)
#pragma unroll
            for (int c = 0; c < 4; c++) acc[i][j][c] = 0.f;

    auto issue = [&](int k0, int s) {
        const uint32_t sa = sbase + (uint32_t)s * G_STGB;
#pragma unroll
        for (int i = 0; i < 2; i++) {
            int idx = tid + (i << 8);
            int row = idx >> 2, c8 = (idx & 3) << 3;
            uint32_t off = (uint32_t)(row * APAD + c8) * 2;
            cp16(sa + off,         Ah + (size_t)(bm + row) * K + k0 + c8);
            cp16(sa + G_ASB + off, Bsel + (size_t)(bnl + row) * K + k0 + c8);
        }
        CP_COMMIT();
    };

    const int nk = K >> 5;
    issue(0, 0);
    issue(32, 1);
    issue(64, 2);

    const int ab = wm * 32, bb = wn * 64;
    const uint32_t aoff = (uint32_t)((ab + r16) * APAD + q8) * 2;
    const uint32_t boff = (uint32_t)((bb + r16) * APAD + q8) * 2;

    for (int it = 0; it < nk; ++it) {
        if (it < nk - 2)      CP_WAIT(2);
        else if (it < nk - 1) CP_WAIT(1);
        else                  CP_WAIT(0);
        __syncthreads();
        if (it + 3 < nk) issue((it + 3) << 5, (it + 3) & 3);

        const uint32_t sA = sbase + (uint32_t)(it & 3) * G_STGB;
        const uint32_t sB = sA + G_ASB;

#pragma unroll
        for (int ks = 0; ks < 2; ks++) {
            const uint32_t kb2 = (uint32_t)(ks * 16) * 2;
            uint32_t ah[2][4];
#pragma unroll
            for (int i = 0; i < 2; i++)
                ldsm_x4(ah[i], sA + aoff + kb2 + (uint32_t)(i * 16 * APAD) * 2);
#pragma unroll
            for (int jp = 0; jp < 4; jp++) {
                uint32_t rb4[4];
                ldsm_x4(rb4, sB + boff + kb2 + (uint32_t)(jp * 16 * APAD) * 2);
                mma_h(acc[0][2 * jp],     ah[0], rb4[0], rb4[2]);
                mma_h(acc[0][2 * jp + 1], ah[0], rb4[1], rb4[3]);
                mma_h(acc[1][2 * jp],     ah[1], rb4[0], rb4[2]);
                mma_h(acc[1][2 * jp + 1], ah[1], rb4[1], rb4[3]);
            }
        }
        __syncthreads();
    }

    // ---- epilogue ----
    if (MODE == 2) {
        // route: q fp32 / k fp32 / v fp16
        const bool isv = (bn >= HIDN + KVW);
        float* dst32 = (bn < HIDN) ? g_q : g_k;
        const int stride = (bn < HIDN) ? HIDN : KVW;
        const int c0 = (bn < HIDN) ? bn : (bn < HIDN + KVW ? bn - HIDN
                                                           : bn - HIDN - KVW);
#pragma unroll
        for (int j = 0; j < 8; j++) {
            const int cl = wn * 64 + j * 8 + 2 * t;
            const float bx = g_bias[bn + cl], by = g_bias[bn + cl + 1];
#pragma unroll
            for (int i = 0; i < 2; i++) {
                const int row = bm + wm * 32 + i * 16 + g;
                float o0 = acc[i][j][0] + bx, o1 = acc[i][j][1] + by;
                float o2 = acc[i][j][2] + bx, o3 = acc[i][j][3] + by;
                if (isv) {
                    *(__half2*)(g_vh + (size_t)row * KVW + c0 + cl) =
                        __floats2half2_rn(o0, o1);
                    *(__half2*)(g_vh + (size_t)(row + 8) * KVW + c0 + cl) =
                        __floats2half2_rn(o2, o3);
                } else {
                    *(float2*)(dst32 + (size_t)row * stride + c0 + cl) =
                        make_float2(o0, o1);
                    *(float2*)(dst32 + (size_t)(row + 8) * stride + c0 + cl) =
                        make_float2(o2, o3);
                }
            }
        }
    } else {
#pragma unroll
        for (int j = 0; j < 8; j++) {
            const int col = bn + wn * 64 + j * 8 + 2 * t;
            float2 bv = make_float2(0.f, 0.f);
            if (bias) { bv.x = bias[col]; bv.y = bias[col + 1]; }
#pragma unroll
            for (int i = 0; i < 2; i++) {
                const int row = bm + wm * 32 + i * 16 + g;
                *(float2*)(C + (size_t)row * N + col) =
                    make_float2(acc[i][j][0] + bv.x, acc[i][j][1] + bv.y);
                *(float2*)(C + (size_t)(row + 8) * N + col) =
                    make_float2(acc[i][j][2] + bv.x, acc[i][j][3] + bv.y);
            }
        }
    }
}

// ============================================================
// Fused RMSNorm + RoPE: one warp per (token, head) row.
// ============================================================
__global__ __launch_bounds__(256)
void rmsrope_kernel(const float* __restrict__ q, const float* __restrict__ k,
                    __half* __restrict__ qh, __half* __restrict__ kh,
                    const float* __restrict__ cosb, const float* __restrict__ sinb,
                    const float* __restrict__ qw, const float* __restrict__ kw)
{
    const int wid  = threadIdx.x >> 5, lane = threadIdx.x & 31;
    const int s    = blockIdx.x * 8 + wid;
    const int hh   = blockIdx.y;

    const float* base;
    __half* outp;
    const float* w;
    if (hh < NH) {
        base = q + (size_t)s * HIDN + hh * DH;
        outp = qh + (size_t)s * HIDN + hh * DH;
        w = qw;
    } else {
        base = k + (size_t)s * KVW + (hh - NH) * DH;
        outp = kh + (size_t)s * KVW + (hh - NH) * DH;
        w = kw;
    }

    float4 v = *(const float4*)(base + 4 * lane);
    float ss = v.x * v.x + v.y * v.y + v.z * v.z + v.w * v.w;
#pragma unroll
    for (int off = 16; off >= 1; off >>= 1)
        ss += __shfl_xor_sync(0xffffffffu, ss, off);
    const float inv = rsqrtf(ss * (1.f / 128.f) + 1e-6f);

    float4 wv = *(const float4*)(w + 4 * lane);
    float4 nv;
    nv.x = wv.x * v.x * inv; nv.y = wv.y * v.y * inv;
    nv.z = wv.z * v.z * inv; nv.w = wv.w * v.w * inv;

    float4 ov;
    ov.x = __shfl_xor_sync(0xffffffffu, nv.x, 16);
    ov.y = __shfl_xor_sync(0xffffffffu, nv.y, 16);
    ov.z = __shfl_xor_sync(0xffffffffu, nv.z, 16);
    ov.w = __shfl_xor_sync(0xffffffffu, nv.w, 16);
    const float sgn = (lane < 16) ? -1.f : 1.f;

    const float4 cv = *(const float4*)(cosb + (size_t)s * DH + 4 * lane);
    const float4 sv = *(const float4*)(sinb + (size_t)s * DH + 4 * lane);
    float r0 = nv.x * cv.x + sgn * ov.x * sv.x;
    float r1 = nv.y * cv.y + sgn * ov.y * sv.y;
    float r2 = nv.z * cv.z + sgn * ov.z * sv.z;
    float r3 = nv.w * cv.w + sgn * ov.w * sv.w;

    __half2 h01 = __floats2half2_rn(r0, r1);
    __half2 h23 = __floats2half2_rn(r2, r3);
    uint2 pack;
    pack.x = *(uint32_t*)&h01;
    pack.y = *(uint32_t*)&h23;
    *(uint2*)(outp + 4 * lane) = pack;
}

// ============================================================
// Flash attention, fp16 mma, causal. BM=128, BN=64.
// 2-stage cp.async K/V pipeline -> 2 CTAs/SM.
// ============================================================
#define QSTR 136
#define A_QB   (128 * QSTR * 2)
#define A_KB   (64 * QSTR * 2)
#define A_STGB (2 * A_KB)
#define ATTN_SMEM (A_QB + 2 * A_STGB)   // 104448 B

__global__ __launch_bounds__(256, 2)
void attn_h(const __half* __restrict__ Q, const __half* __restrict__ K,
            const __half* __restrict__ V, __half* __restrict__ Oh)
{
    extern __shared__ __half sh[];
    __half* Qs = sh;
    const uint32_t sbase = (uint32_t)__cvta_generic_to_shared(sh);

    const int tid  = threadIdx.x;
    const int lane = tid & 31, wid = tid >> 5;
    const int g = lane >> 2, t = lane & 3;
    const int h  = blockIdx.y;
    const int tq = (gridDim.x - 1) - blockIdx.x;
    const int row0 = tq * 128;
    const int kh = h >> 1;
    const int row_l = wid * 16;

    const int r16 = lane & 15;
    const int q8  = (lane >> 4) << 3;
    const uint32_t qoff = (uint32_t)((row_l + r16) * QSTR + q8) * 2;
    const uint32_t koff = (uint32_t)(r16 * QSTR + q8) * 2;
    const int vm = lane >> 3, vri = lane & 7;
    const uint32_t voff =
        (uint32_t)((vri + ((vm >> 1) << 3)) * QSTR + ((vm & 1) << 3)) * 2;

    const int njt = 2 * tq + 2;

    auto issue = [&](int jt, int s) {
        const int col0 = jt * 64;
        const uint32_t base = sbase + A_QB + (uint32_t)s * A_STGB;
#pragma unroll
        for (int i = 0; i < 4; i++) {
            int idx = tid + (i << 8);
            int row = idx >> 4, c8 = (idx & 15) << 3;
            uint32_t off = (uint32_t)(row * QSTR + c8) * 2;
            cp16(base + off,        K + (size_t)(col0 + row) * KVW + kh * DH + c8);
            cp16(base + A_KB + off, V + (size_t)(col0 + row) * KVW + kh * DH + c8);
        }
        CP_COMMIT();
    };

#pragma unroll
    for (int it = tid; it < 128 * 16; it += 256) {
        int r = it >> 4, c8 = (it & 15) << 3;
        *(uint4*)(Qs + r * QSTR + c8) =
            *(const uint4*)(Q + (size_t)(row0 + r) * HIDN + h * DH + c8);
    }

    issue(0, 0);
    issue(1, 1);

    float o[16][4];
#pragma unroll
    for (int jj = 0; jj < 16; jj++)
#pragma unroll
        for (int c = 0; c < 4; c++) o[jj][c] = 0.f;
    float m0 = -INFINITY, m1 = -INFINITY, l0 = 0.f, l1 = 0.f;

    for (int jt = 0; jt < njt; jt++) {
        if (jt < njt - 1) CP_WAIT(1); else CP_WAIT(0);
        __syncthreads();

        const bool skip = (jt == 2 * tq + 1 && wid < 4);
        if (!skip) {
            const uint32_t sK = sbase + A_QB + (uint32_t)(jt & 1) * A_STGB;
            const uint32_t sV = sK + A_KB;

            // ---- QK^T ----
            float s[8][4];
#pragma unroll
            for (int j = 0; j < 8; j++)
#pragma unroll
                for (int c = 0; c < 4; c++) s[j][c] = 0.f;

#pragma unroll
            for (int ks = 0; ks < 8; ks++) {
                const uint32_t kb2 = (uint32_t)(ks * 16) * 2;
                uint32_t av[4];
                ldsm_x4(av, sbase + qoff + kb2);
#pragma unroll
                for (int jp = 0; jp < 4; jp++) {
                    uint32_t kb4[4];
                    ldsm_x4(kb4, sK + koff + kb2 + (uint32_t)(jp * 16 * QSTR) * 2);
                    mma_h(s[2 * jp],     av, kb4[0], kb4[2]);
                    mma_h(s[2 * jp + 1], av, kb4[1], kb4[3]);
                }
            }

            // ---- softmax ----
            const bool diag = (jt >= 2 * tq);
            const int crel = (jt - 2 * tq) * 64;
            const int rg = row_l + g;
            float mx0 = -INFINITY, mx1 = -INFINITY;
#pragma unroll
            for (int j = 0; j < 8; j++) {
                float v0 = s[j][0] * ATT_SCALE, v1 = s[j][1] * ATT_SCALE;
                float v2 = s[j][2] * ATT_SCALE, v3 = s[j][3] * ATT_SCALE;
                if (diag) {
                    int c = crel + 8 * j + 2 * t;
                    if (c     > rg)     v0 = -1e30f;
                    if (c + 1 > rg)     v1 = -1e30f;
                    if (c     > rg + 8) v2 = -1e30f;
                    if (c + 1 > rg + 8) v3 = -1e30f;
                }
                s[j][0] = v0; s[j][1] = v1; s[j][2] = v2; s[j][3] = v3;
                mx0 = fmaxf(mx0, fmaxf(v0, v1));
                mx1 = fmaxf(mx1, fmaxf(v2, v3));
            }
            mx0 = fmaxf(mx0, __shfl_xor_sync(0xffffffffu, mx0, 1));
            mx0 = fmaxf(mx0, __shfl_xor_sync(0xffffffffu, mx0, 2));
            mx1 = fmaxf(mx1, __shfl_xor_sync(0xffffffffu, mx1, 1));
            mx1 = fmaxf(mx1, __shfl_xor_sync(0xffffffffu, mx1, 2));

            const float mn0 = fmaxf(m0, mx0), mn1 = fmaxf(m1, mx1);
            const float al0 = __expf(m0 - mn0), al1 = __expf(m1 - mn1);
            float ls0 = 0.f, ls1 = 0.f;
#pragma unroll
            for (int j = 0; j < 8; j++) {
                float p0 = __expf(s[j][0] - mn0), p1 = __expf(s[j][1] - mn0);
                float p2 = __expf(s[j][2] - mn1), p3 = __expf(s[j][3] - mn1);
                s[j][0] = p0; s[j][1] = p1; s[j][2] = p2; s[j][3] = p3;
                ls0 += p0 + p1;
                ls1 += p2 + p3;
            }
            ls0 += __shfl_xor_sync(0xffffffffu, ls0, 1);
            ls0 += __shfl_xor_sync(0xffffffffu, ls0, 2);
            ls1 += __shfl_xor_sync(0xffffffffu, ls1, 1);
            ls1 += __shfl_xor_sync(0xffffffffu, ls1, 2);

            l0 = l0 * al0 + ls0;
            l1 = l1 * al1 + ls1;
            m0 = mn0; m1 = mn1;
#pragma unroll
            for (int jj = 0; jj < 16; jj++) {
                o[jj][0] *= al0; o[jj][1] *= al0;
                o[jj][2] *= al1; o[jj][3] *= al1;
            }

            // ---- PV ----
#pragma unroll
            for (int s2 = 0; s2 < 4; s2++) {
                __half2 t0 = __floats2half2_rn(s[2 * s2][0],     s[2 * s2][1]);
                __half2 t1 = __floats2half2_rn(s[2 * s2][2],     s[2 * s2][3]);
                __half2 t2 = __floats2half2_rn(s[2 * s2 + 1][0], s[2 * s2 + 1][1]);
                __half2 t3 = __floats2half2_rn(s[2 * s2 + 1][2], s[2 * s2 + 1][3]);
                uint32_t pa[4];
                pa[0] = *(uint32_t*)&t0;
                pa[1] = *(uint32_t*)&t1;
                pa[2] = *(uint32_t*)&t2;
                pa[3] = *(uint32_t*)&t3;
                const uint32_t vrow2 = (uint32_t)(s2 * 16 * QSTR) * 2;
#pragma unroll
                for (int djp = 0; djp < 8; djp++) {
                    uint32_t vb[4];
                    ldsm_x4_t(vb, sV + voff + vrow2 + (uint32_t)(djp * 16) * 2);
                    mma_h(o[2 * djp],     pa, vb[0], vb[2]);
                    mma_h(o[2 * djp + 1], pa, vb[1], vb[3]);
                }
            }
        }
        __syncthreads();
        if (jt + 2 < njt) issue(jt + 2, jt & 1);
    }

    // epilogue
    const float i0 = 1.f / l0, i1 = 1.f / l1;
    const int gr0 = row0 + row_l + g, gr1 = gr0 + 8;
#pragma unroll
    for (int jj = 0; jj < 16; jj++) {
        const int col = h * DH + jj * 8 + 2 * t;
        *(__half2*)(Oh + (size_t)gr0 * HIDN + col) =
            __floats2half2_rn(o[jj][0] * i0, o[jj][1] * i0);
        *(__half2*)(Oh + (size_t)gr1 * HIDN + col) =
            __floats2half2_rn(o[jj][2] * i1, o[jj][3] * i1);
    }
}

// ============================================================
// launch
// ============================================================
extern "C" void kernel_launch(void* const* d_in, const int* in_sizes, int n_in,
                              void* d_out, int out_size)
{
    const float* x    = (const float*)d_in[0];
    const float* cosb = (const float*)d_in[1];
    const float* sinb = (const float*)d_in[2];
    // d_in[3] = mask: ignored (exactly causal, implemented analytically)
    const float* Wq = (const float*)d_in[4];
    const float* bq = (const float*)d_in[5];
    const float* Wk = (const float*)d_in[6];
    const float* bk = (const float*)d_in[7];
    const float* Wv = (const float*)d_in[8];
    const float* bv = (const float*)d_in[9];
    const float* Wo = (const float*)d_in[10];
    const float* qw = (const float*)d_in[11];
    const float* kw = (const float*)d_in[12];
    float* out = (float*)d_out;

    float *qp, *kp;
    __half *xh, *wo, *qhp, *khp, *vhp, *oh;
    cudaGetSymbolAddress((void**)&qp,  g_q);
    cudaGetSymbolAddress((void**)&kp,  g_k);
    cudaGetSymbolAddress((void**)&xh,  g_xh);
    cudaGetSymbolAddress((void**)&wo,  g_wo);
    cudaGetSymbolAddress((void**)&qhp, g_qh);
    cudaGetSymbolAddress((void**)&khp, g_kh);
    cudaGetSymbolAddress((void**)&vhp, g_vh);
    cudaGetSymbolAddress((void**)&oh,  g_oh);

    cudaFuncSetAttribute(attn_h, cudaFuncAttributeMaxDynamicSharedMemorySize,
                         ATTN_SMEM);
    cudaFuncSetAttribute(gemm_a<0>, cudaFuncAttributeMaxDynamicSharedMemorySize,
                         G_SMEM);
    cudaFuncSetAttribute(gemm_a<2>, cudaFuncAttributeMaxDynamicSharedMemorySize,
                         G_SMEM);

    f2h_all<<<(N4_TOT + 255) / 256, 256>>>((const float4*)x, (const float4*)Wq,
                                           (const float4*)Wk, (const float4*)Wv,
                                           (const float4*)Wo, bq, bk, bv);

    dim3 blk(256);
    // fused QKV projection: N = 4096 routed to q(fp32)/k(fp32)/v(fp16)
    gemm_a<2><<<dim3(32, 32), blk, G_SMEM>>>(xh, nullptr, nullptr, nullptr,
                                             S_LEN, NQKV, HIDN);

    rmsrope_kernel<<<dim3(S_LEN / 8, NH + NKV), 256>>>(qp, kp, qhp, khp,
                                                       cosb, sinb, qw, kw);

    attn_h<<<dim3(32, NH), 256, ATTN_SMEM>>>(qhp, khp, vhp, oh);

    gemm_a<0><<<dim3(16, 32), blk, G_SMEM>>>(oh, wo, nullptr, out,
                                             S_LEN, HIDN, HIDN);
}